// round 4
// baseline (speedup 1.0000x reference)
#include <cuda_runtime.h>
#include <cuda.h>
#include <math.h>
#include <stdint.h>

#define Bn  2
#define Tn  2048
#define Dn  1024
#define Hn  16
#define HDn 64
#define Mn  (Bn * Tn)   // 4096

// -------- scratch (static device globals; no allocations allowed) --------
__device__ float g_Q[(size_t)Bn * Hn * Tn * HDn];   // [B,H,T,64] -> rows [bh*T + t]
__device__ float g_K[(size_t)Bn * Hn * Tn * HDn];
__device__ float g_V[(size_t)Bn * Hn * Tn * HDn];
__device__ float g_O[(size_t)Mn * Dn];              // [B*T, D]
__device__ float g_P[(size_t)Mn * Dn];              // pre-LN

// ---------------- device helpers ----------------
__device__ __forceinline__ unsigned fu(float x) { return __float_as_uint(x); }
__device__ __forceinline__ uint32_t s2u(const void* p) {
    return (uint32_t)__cvta_generic_to_shared(p);
}

// D += A(16x8, row) * B(8x8, col), tf32 in (HW-truncated fp32), f32 out
__device__ __forceinline__ void mma8(float* d, const unsigned* a,
                                     unsigned b0, unsigned b1) {
    asm volatile(
        "mma.sync.aligned.m16n8k8.row.col.f32.tf32.tf32.f32 "
        "{%0,%1,%2,%3},{%4,%5,%6,%7},{%8,%9},{%0,%1,%2,%3};"
        : "+f"(d[0]), "+f"(d[1]), "+f"(d[2]), "+f"(d[3])
        : "r"(a[0]), "r"(a[1]), "r"(a[2]), "r"(a[3]), "r"(b0), "r"(b1));
}

__device__ __forceinline__ void cpa16(float* dst_smem, const float* src) {
    unsigned d = (unsigned)__cvta_generic_to_shared(dst_smem);
    asm volatile("cp.async.cg.shared.global [%0], [%1], 16;" :: "r"(d), "l"(src));
}
__device__ __forceinline__ void cp_commit() { asm volatile("cp.async.commit_group;"); }
template<int N> __device__ __forceinline__ void cp_wait() {
    asm volatile("cp.async.wait_group %0;" :: "n"(N));
}

__device__ __forceinline__ void mbar_init(uint32_t m, uint32_t cnt) {
    asm volatile("mbarrier.init.shared.b64 [%0], %1;" :: "r"(m), "r"(cnt) : "memory");
}
__device__ __forceinline__ void mbar_expect(uint32_t m, uint32_t bytes) {
    asm volatile("mbarrier.arrive.expect_tx.shared.b64 _, [%0], %1;"
                 :: "r"(m), "r"(bytes) : "memory");
}
__device__ __forceinline__ void mbar_wait(uint32_t m, uint32_t parity) {
    asm volatile(
        "{\n\t"
        ".reg .pred P1;\n\t"
        "WAIT_%=:\n\t"
        "mbarrier.try_wait.parity.acquire.cta.shared::cta.b64 P1, [%0], %1, 0x989680;\n\t"
        "@P1 bra.uni DONE_%=;\n\t"
        "bra.uni WAIT_%=;\n\t"
        "DONE_%=:\n\t"
        "}"
        :: "r"(m), "r"(parity) : "memory");
}
__device__ __forceinline__ void tma2d(uint32_t dst, const CUtensorMap* tm,
                                      int x, int y, uint32_t mbar) {
    asm volatile(
        "cp.async.bulk.tensor.2d.shared::cta.global.tile.mbarrier::complete_tx::bytes "
        "[%0], [%1, {%2, %3}], [%4];"
        :: "r"(dst), "l"(tm), "r"(x), "r"(y), "r"(mbar) : "memory");
}

// SW128 swizzled float index within a tile whose rows are 128B (32 floats):
// element (row, col) -> row*32 + (col ^ ((row&7)<<2))
__device__ __forceinline__ int swzi(int row, int col) {
    return row * 32 + (col ^ ((row & 7) << 2));
}

// =========================================================================
// Tensor-core GEMM, single-pass tf32, 128x128 CTA tile, Kchunk=32,
// TMA + mbarrier double-buffered. 256 threads = 8 warps (4m x 2n).
// Stage layout (32KB): A[128][32] SW128 (16KB) | B: 4 subtiles [32k][32n] SW128.
// =========================================================================
#define G_STAGE_F 8192                 // floats per stage
#define G_STAGE_B 32768                // bytes per stage
#define GEMM_SMEM_BYTES (2 * G_STAGE_B + 1024)

__device__ __forceinline__ void gemm_issue_tma(
    uint32_t stage_u, const CUtensorMap* tmA, const CUtensorMap* tmW,
    int m0, int n0, int k0, uint32_t mb)
{
    mbar_expect(mb, G_STAGE_B);
    tma2d(stage_u, tmA, k0, m0, mb);                       // A: 32k x 128m
#pragma unroll
    for (int t = 0; t < 4; t++)
        tma2d(stage_u + 16384 + t * 4096, tmW, n0 + 32 * t, k0, mb);  // B: 32n x 32k
}

__device__ __forceinline__ void gemm_main(
    const CUtensorMap* tmA, const CUtensorMap* tmW,
    const float* __restrict__ bias, const float* __restrict__ resid,
    float* __restrict__ out, int mode)
{
    extern __shared__ float smraw[];
    float* sm = (float*)(((uintptr_t)smraw + 1023) & ~(uintptr_t)1023);
    __shared__ uint64_t mbar_s[2];

    const int tid = threadIdx.x, lane = tid & 31, w = tid >> 5;
    const int g = lane >> 2, tig = lane & 3;
    const int wm = w & 3, wn = w >> 2;
    const int m0 = blockIdx.y * 128, n0 = blockIdx.x * 128;

    const uint32_t mb0 = s2u(&mbar_s[0]), mb1 = s2u(&mbar_s[1]);
    const uint32_t smu = s2u(sm);

    if (tid == 0) { mbar_init(mb0, 1); mbar_init(mb1, 1); }
    __syncthreads();
    if (tid == 0) {
        gemm_issue_tma(smu, tmA, tmW, m0, n0, 0, mb0);
        gemm_issue_tma(smu + G_STAGE_B, tmA, tmW, m0, n0, 32, mb1);
    }

    float acc[2][8][4];
#pragma unroll
    for (int mt = 0; mt < 2; mt++)
#pragma unroll
        for (int nt = 0; nt < 8; nt++)
#pragma unroll
            for (int j = 0; j < 4; j++) acc[mt][nt][j] = 0.f;

    for (int c = 0; c < 32; c++) {
        mbar_wait((c & 1) ? mb1 : mb0, (c >> 1) & 1);
        float* As = sm + (c & 1) * G_STAGE_F;
        float* Bs = As + 4096;

#pragma unroll
        for (int kk = 0; kk < 4; kk++) {
            const int k = kk * 8 + tig;
            unsigned ah[2][4];
#pragma unroll
            for (int mt = 0; mt < 2; mt++) {
                int m = wm * 32 + mt * 16 + g;
                ah[mt][0] = fu(As[swzi(m, k)]);
                ah[mt][1] = fu(As[swzi(m + 8, k)]);
                ah[mt][2] = fu(As[swzi(m, k + 4)]);
                ah[mt][3] = fu(As[swzi(m + 8, k + 4)]);
            }
#pragma unroll
            for (int nt = 0; nt < 8; nt++) {
                int nl = wn * 64 + nt * 8 + g;
                const float* Bt = Bs + (nl >> 5) * 1024;
                unsigned b0 = fu(Bt[swzi(k, nl & 31)]);
                unsigned b1 = fu(Bt[swzi(k + 4, nl & 31)]);
                mma8(acc[0][nt], ah[0], b0, b1);
                mma8(acc[1][nt], ah[1], b0, b1);
            }
        }
        __syncthreads();
        if (c + 2 < 32 && tid == 0) {
            gemm_issue_tma(smu + (c & 1) * G_STAGE_B, tmA, tmW,
                           m0, n0, (c + 2) * 32, (c & 1) ? mb1 : mb0);
        }
    }

    // epilogue
#pragma unroll
    for (int mt = 0; mt < 2; mt++) {
#pragma unroll
        for (int nt = 0; nt < 8; nt++) {
            int r0 = m0 + wm * 32 + mt * 16 + g;
            int n = n0 + wn * 64 + nt * 8 + 2 * tig;
            float bx = bias[n], by = bias[n + 1];
            if (mode == 0) {
#pragma unroll
                for (int rp = 0; rp < 2; rp++) {
                    int r = r0 + rp * 8;
                    int bb = r >> 11, t = r & (Tn - 1);
                    int h = n >> 6, hd = n & 63;
                    float2 val = make_float2(acc[mt][nt][2 * rp] + bx,
                                             acc[mt][nt][2 * rp + 1] + by);
                    *(float2*)&out[((((size_t)bb * Hn + h) * Tn) + t) * HDn + hd] = val;
                }
            } else {
#pragma unroll
                for (int rp = 0; rp < 2; rp++) {
                    int r = r0 + rp * 8;
                    size_t off = (size_t)r * Dn + n;
                    float2 rv = *(const float2*)&resid[off];
                    float2 val = make_float2(acc[mt][nt][2 * rp] + bx + rv.x,
                                             acc[mt][nt][2 * rp + 1] + by + rv.y);
                    *(float2*)&out[off] = val;
                }
            }
        }
    }
}

__global__ void __launch_bounds__(256, 2) qkv_gemm(
    const __grid_constant__ CUtensorMap tmA,
    const __grid_constant__ CUtensorMap tmWq,
    const __grid_constant__ CUtensorMap tmWk,
    const __grid_constant__ CUtensorMap tmWv,
    const float* __restrict__ bq, const float* __restrict__ bk,
    const float* __restrict__ bv,
    float* __restrict__ gQ, float* __restrict__ gK, float* __restrict__ gV)
{
    const CUtensorMap* tw; const float* b; float* o;
    if (blockIdx.z == 0)      { tw = &tmWq; b = bq; o = gQ; }
    else if (blockIdx.z == 1) { tw = &tmWk; b = bk; o = gK; }
    else                      { tw = &tmWv; b = bv; o = gV; }
    gemm_main(&tmA, tw, b, nullptr, o, 0);
}

__global__ void __launch_bounds__(256, 2) oproj_gemm(
    const __grid_constant__ CUtensorMap tmA,
    const __grid_constant__ CUtensorMap tmW,
    const float* __restrict__ b, const float* __restrict__ resid,
    float* __restrict__ out)
{
    gemm_main(&tmA, &tmW, b, resid, out, 1);
}

// =========================================================================
// Tensor-core flash attention, TMA K/V loads, mbarrier double-buffered.
// CTA = (bh, 128-query tile), 8 warps x 16 query rows. K-tiles of 64.
// smem: Q[128][68] (reused as P) | 2 stages x { K 2x[64][32] SW128,
//                                               V 2x[64][32] SW128 } (32KB each)
// =========================================================================
#define A_QS (128 * 68)               // floats
#define A_STAGE_F 8192                // floats per stage (K 4096 + V 4096)
#define A_STAGE_B 32768
#define ATT_SMEM_BYTES (A_QS * 4 + 2 * A_STAGE_B + 1024)

__device__ __forceinline__ void attn_issue_tma(
    uint32_t stage_u, const CUtensorMap* tmK, const CUtensorMap* tmV,
    int row0, uint32_t mb)
{
    mbar_expect(mb, A_STAGE_B);
    tma2d(stage_u,         tmK, 0,  row0, mb);
    tma2d(stage_u + 8192,  tmK, 32, row0, mb);
    tma2d(stage_u + 16384, tmV, 0,  row0, mb);
    tma2d(stage_u + 24576, tmV, 32, row0, mb);
}

__global__ void __launch_bounds__(256, 2) attn_tc(
    const __grid_constant__ CUtensorMap tmK,
    const __grid_constant__ CUtensorMap tmV,
    const float* __restrict__ gQ, float* __restrict__ gO)
{
    extern __shared__ float smraw[];
    float* sm = (float*)(((uintptr_t)smraw + 1023) & ~(uintptr_t)1023);
    float* Qs = sm;                    // 8704 floats (34816 B, 1024-aligned size)
    float* buf = sm + A_QS;
    __shared__ uint64_t mbar_s[2];

    const int tid = threadIdx.x, lane = tid & 31, w = tid >> 5;
    const int g = lane >> 2, tig = lane & 3;
    const int bh = blockIdx.y;
    const int q0 = blockIdx.x << 7;
    const int b = bh >> 4, h = bh & 15;
    const int rb = w * 16;
    const int krow0 = bh * Tn;

    const uint32_t mb0 = s2u(&mbar_s[0]), mb1 = s2u(&mbar_s[1]);
    const uint32_t bufu = s2u(buf);

    if (tid == 0) { mbar_init(mb0, 1); mbar_init(mb1, 1); }
    __syncthreads();

    // stage Q via cp.async (once)
    const float* Q = gQ + ((size_t)krow0 + q0) * HDn;
#pragma unroll
    for (int i = 0; i < 8; i++) {
        int s = tid + i * 256;
        int r = s >> 4, c4 = (s & 15) << 2;
        cpa16(Qs + r * 68 + c4, Q + (size_t)r * HDn + c4);
    }
    cp_commit();

    if (tid == 0) {
        attn_issue_tma(bufu,             &tmK, &tmV, krow0,      mb0);
        attn_issue_tma(bufu + A_STAGE_B, &tmK, &tmV, krow0 + 64, mb1);
    }

    cp_wait<0>();
    __syncthreads();

    // extract Q fragments, fold 1/sqrt(64)
    unsigned qh[8][4];
#pragma unroll
    for (int kk = 0; kk < 8; kk++) {
        int bi = (rb + g) * 68 + kk * 8 + tig;
        qh[kk][0] = fu(Qs[bi] * 0.125f);
        qh[kk][1] = fu(Qs[bi + 8 * 68] * 0.125f);
        qh[kk][2] = fu(Qs[bi + 4] * 0.125f);
        qh[kk][3] = fu(Qs[bi + 8 * 68 + 4] * 0.125f);
    }
    __syncthreads();            // Qs now free -> Ps
    float* Ps = Qs;

    float oacc[8][4];
#pragma unroll
    for (int nt = 0; nt < 8; nt++)
#pragma unroll
        for (int j = 0; j < 4; j++) oacc[nt][j] = 0.f;
    float mst0 = -1e30f, mst1 = -1e30f, lst0 = 0.f, lst1 = 0.f;

    for (int it = 0; it < 32; it++) {
        mbar_wait((it & 1) ? mb1 : mb0, (it >> 1) & 1);
        float* Ks = buf + (it & 1) * A_STAGE_F;
        float* Vs = Ks + 4096;

        // ---- S = Q K^T ----
        float sacc[8][4];
#pragma unroll
        for (int nt = 0; nt < 8; nt++)
#pragma unroll
            for (int j = 0; j < 4; j++) sacc[nt][j] = 0.f;

#pragma unroll
        for (int kk = 0; kk < 8; kk++) {
            int d = kk * 8 + tig;
            const float* Kh = Ks + (d >> 5) * 2048;
            int dl = d & 31;
#pragma unroll
            for (int nt = 0; nt < 8; nt++) {
                int n = nt * 8 + g;
                unsigned b0 = fu(Kh[swzi(n, dl)]);
                unsigned b1 = fu(Kh[swzi(n, dl + 4)]);
                mma8(sacc[nt], qh[kk], b0, b1);
            }
        }

        // ---- online softmax (row quads: lanes xor 1,2) ----
        float mx0 = -1e30f, mx1 = -1e30f;
#pragma unroll
        for (int nt = 0; nt < 8; nt++) {
            mx0 = fmaxf(mx0, fmaxf(sacc[nt][0], sacc[nt][1]));
            mx1 = fmaxf(mx1, fmaxf(sacc[nt][2], sacc[nt][3]));
        }
        mx0 = fmaxf(mx0, __shfl_xor_sync(0xffffffffu, mx0, 1));
        mx0 = fmaxf(mx0, __shfl_xor_sync(0xffffffffu, mx0, 2));
        mx1 = fmaxf(mx1, __shfl_xor_sync(0xffffffffu, mx1, 1));
        mx1 = fmaxf(mx1, __shfl_xor_sync(0xffffffffu, mx1, 2));
        float mn0 = fmaxf(mst0, mx0), mn1 = fmaxf(mst1, mx1);
        float c0 = __expf(mst0 - mn0), c1 = __expf(mst1 - mn1);
        mst0 = mn0; mst1 = mn1;
        float s0 = 0.f, s1 = 0.f;
#pragma unroll
        for (int nt = 0; nt < 8; nt++) {
            float p0 = __expf(sacc[nt][0] - mn0);
            float p1 = __expf(sacc[nt][1] - mn0);
            float p2 = __expf(sacc[nt][2] - mn1);
            float p3 = __expf(sacc[nt][3] - mn1);
            s0 += p0 + p1; s1 += p2 + p3;
            sacc[nt][0] = p0; sacc[nt][1] = p1; sacc[nt][2] = p2; sacc[nt][3] = p3;
            oacc[nt][0] *= c0; oacc[nt][1] *= c0; oacc[nt][2] *= c1; oacc[nt][3] *= c1;
        }
        s0 += __shfl_xor_sync(0xffffffffu, s0, 1);
        s0 += __shfl_xor_sync(0xffffffffu, s0, 2);
        s1 += __shfl_xor_sync(0xffffffffu, s1, 1);
        s1 += __shfl_xor_sync(0xffffffffu, s1, 2);
        lst0 = lst0 * c0 + s0;
        lst1 = lst1 * c1 + s1;

        // write P tile (own warp rows)
#pragma unroll
        for (int nt = 0; nt < 8; nt++) {
            *(float2*)&Ps[(rb + g) * 68 + nt * 8 + 2 * tig] =
                make_float2(sacc[nt][0], sacc[nt][1]);
            *(float2*)&Ps[(rb + g + 8) * 68 + nt * 8 + 2 * tig] =
                make_float2(sacc[nt][2], sacc[nt][3]);
        }
        __syncwarp();

        // ---- O += P V ----
#pragma unroll
        for (int kk = 0; kk < 8; kk++) {
            int ai = (rb + g) * 68 + kk * 8 + tig;
            unsigned a[4] = { fu(Ps[ai]), fu(Ps[ai + 8 * 68]),
                              fu(Ps[ai + 4]), fu(Ps[ai + 8 * 68 + 4]) };
            int j = kk * 8 + tig;
#pragma unroll
            for (int nt = 0; nt < 8; nt++) {
                int d = nt * 8 + g;
                const float* Vh = Vs + (d >> 5) * 2048;
                int dl = d & 31;
                unsigned b0 = fu(Vh[swzi(j, dl)]);
                unsigned b1 = fu(Vh[swzi(j + 4, dl)]);
                mma8(oacc[nt], a, b0, b1);
            }
        }
        __syncthreads();
        if (it + 2 < 32 && tid == 0) {
            attn_issue_tma(bufu + (it & 1) * A_STAGE_B, &tmK, &tmV,
                           krow0 + (it + 2) * 64, (it & 1) ? mb1 : mb0);
        }
    }

    // epilogue
    float i0 = 1.f / lst0, i1 = 1.f / lst1;
    int gr0 = b * Tn + q0 + rb + g;
#pragma unroll
    for (int nt = 0; nt < 8; nt++) {
        int col = h * HDn + nt * 8 + 2 * tig;
        *(float2*)&gO[(size_t)gr0 * Dn + col] =
            make_float2(oacc[nt][0] * i0, oacc[nt][1] * i0);
        *(float2*)&gO[(size_t)(gr0 + 8) * Dn + col] =
            make_float2(oacc[nt][2] * i1, oacc[nt][3] * i1);
    }
}

// =========================================================================
// LayerNorm: 1 block per row, 256 threads, 1 float4 per thread.
// =========================================================================
__global__ void __launch_bounds__(256) ln_kernel(
    const float* __restrict__ P, const float* __restrict__ gw,
    const float* __restrict__ gb, float* __restrict__ out)
{
    const int row = blockIdx.x;
    const int tid = threadIdx.x;
    const float4 v = ((const float4*)(P + (size_t)row * Dn))[tid];

    float s  = v.x + v.y + v.z + v.w;
    float ss = v.x * v.x + v.y * v.y + v.z * v.z + v.w * v.w;
#pragma unroll
    for (int off = 16; off; off >>= 1) {
        s  += __shfl_xor_sync(0xffffffffu, s, off);
        ss += __shfl_xor_sync(0xffffffffu, ss, off);
    }
    __shared__ float sh_s[8], sh_ss[8];
    const int w = tid >> 5, lane = tid & 31;
    if (lane == 0) { sh_s[w] = s; sh_ss[w] = ss; }
    __syncthreads();
    if (w == 0) {
        float s2  = (lane < 8) ? sh_s[lane]  : 0.f;
        float ss2 = (lane < 8) ? sh_ss[lane] : 0.f;
#pragma unroll
        for (int off = 4; off; off >>= 1) {
            s2  += __shfl_xor_sync(0xffffffffu, s2, off);
            ss2 += __shfl_xor_sync(0xffffffffu, ss2, off);
        }
        if (lane == 0) { sh_s[0] = s2; sh_ss[0] = ss2; }
    }
    __syncthreads();

    const float mu  = sh_s[0] * (1.0f / Dn);
    const float var = sh_ss[0] * (1.0f / Dn) - mu * mu;
    const float rs  = rsqrtf(var + 1e-5f);

    const float4 g = ((const float4*)gw)[tid];
    const float4 bb = ((const float4*)gb)[tid];
    float4 r;
    r.x = (v.x - mu) * rs * g.x + bb.x;
    r.y = (v.y - mu) * rs * g.y + bb.y;
    r.z = (v.z - mu) * rs * g.z + bb.z;
    r.w = (v.w - mu) * rs * g.w + bb.w;
    ((float4*)(out + (size_t)row * Dn))[tid] = r;
}

// =========================================================================
// Host side: tensor map construction + launches
// =========================================================================
typedef CUresult (*PFN_tmencode)(
    CUtensorMap*, CUtensorMapDataType, cuuint32_t, void*,
    const cuuint64_t*, const cuuint64_t*, const cuuint32_t*, const cuuint32_t*,
    CUtensorMapInterleave, CUtensorMapSwizzle, CUtensorMapL2promotion,
    CUtensorMapFloatOOBfill);

static void mkmap2d(PFN_tmencode enc, CUtensorMap* tm, const void* ptr,
                    unsigned long long d0, unsigned long long d1,
                    unsigned long long stride_bytes,
                    unsigned b0, unsigned b1)
{
    cuuint64_t dims[2]   = {(cuuint64_t)d0, (cuuint64_t)d1};
    cuuint64_t str[1]    = {(cuuint64_t)stride_bytes};
    cuuint32_t box[2]    = {b0, b1};
    cuuint32_t es[2]     = {1, 1};
    enc(tm, CU_TENSOR_MAP_DATA_TYPE_FLOAT32, 2, (void*)ptr, dims, str, box, es,
        CU_TENSOR_MAP_INTERLEAVE_NONE, CU_TENSOR_MAP_SWIZZLE_128B,
        CU_TENSOR_MAP_L2_PROMOTION_L2_128B, CU_TENSOR_MAP_FLOAT_OOB_FILL_NONE);
}

extern "C" void kernel_launch(void* const* d_in, const int* in_sizes, int n_in,
                              void* d_out, int out_size)
{
    const float* x  = (const float*)d_in[0];
    const float* Wq = (const float*)d_in[1];
    const float* bq = (const float*)d_in[2];
    const float* Wk = (const float*)d_in[3];
    const float* bk = (const float*)d_in[4];
    const float* Wv = (const float*)d_in[5];
    const float* bv = (const float*)d_in[6];
    const float* Wo = (const float*)d_in[7];
    const float* bo = (const float*)d_in[8];
    const float* lg = (const float*)d_in[9];
    const float* lb = (const float*)d_in[10];
    float* out = (float*)d_out;

    float *gQ, *gK, *gV, *gO, *gP;
    cudaGetSymbolAddress((void**)&gQ, g_Q);
    cudaGetSymbolAddress((void**)&gK, g_K);
    cudaGetSymbolAddress((void**)&gV, g_V);
    cudaGetSymbolAddress((void**)&gO, g_O);
    cudaGetSymbolAddress((void**)&gP, g_P);

    // driver entry point for tensor-map encode (no libcuda link needed)
    void* fp = nullptr;
    cudaDriverEntryPointQueryResult st;
    cudaGetDriverEntryPointByVersion("cuTensorMapEncodeTiled", &fp, 12000,
                                     cudaEnableDefault, &st);
    PFN_tmencode enc = (PFN_tmencode)fp;

    CUtensorMap tmX, tmO, tmWq, tmWk, tmWv, tmWo, tmK, tmV;
    // activations [4096 m][1024 k]: box 32k x 128m
    mkmap2d(enc, &tmX, x,  1024, 4096, 4096ULL, 32, 128);
    mkmap2d(enc, &tmO, gO, 1024, 4096, 4096ULL, 32, 128);
    // weights [1024 k][1024 n]: box 32n x 32k
    mkmap2d(enc, &tmWq, Wq, 1024, 1024, 4096ULL, 32, 32);
    mkmap2d(enc, &tmWk, Wk, 1024, 1024, 4096ULL, 32, 32);
    mkmap2d(enc, &tmWv, Wv, 1024, 1024, 4096ULL, 32, 32);
    mkmap2d(enc, &tmWo, Wo, 1024, 1024, 4096ULL, 32, 32);
    // K/V [65536 rows][64 d]: box 32d x 64rows
    mkmap2d(enc, &tmK, gK, 64, (unsigned long long)Bn * Hn * Tn, 256ULL, 32, 64);
    mkmap2d(enc, &tmV, gV, 64, (unsigned long long)Bn * Hn * Tn, 256ULL, 32, 64);

    cudaFuncSetAttribute(qkv_gemm, cudaFuncAttributeMaxDynamicSharedMemorySize,
                         GEMM_SMEM_BYTES);
    cudaFuncSetAttribute(oproj_gemm, cudaFuncAttributeMaxDynamicSharedMemorySize,
                         GEMM_SMEM_BYTES);
    cudaFuncSetAttribute(attn_tc, cudaFuncAttributeMaxDynamicSharedMemorySize,
                         ATT_SMEM_BYTES);

    qkv_gemm<<<dim3(Dn / 128, Mn / 128, 3), 256, GEMM_SMEM_BYTES>>>(
        tmX, tmWq, tmWk, tmWv, bq, bk, bv, gQ, gK, gV);

    attn_tc<<<dim3(Tn / 128, Bn * Hn), 256, ATT_SMEM_BYTES>>>(tmK, tmV, gQ, gO);

    oproj_gemm<<<dim3(Dn / 128, Mn / 128), 256, GEMM_SMEM_BYTES>>>(
        tmO, tmWo, bo, x, gP);

    ln_kernel<<<Mn, 256>>>(gP, lg, lb, out);
}

// round 5
// speedup vs baseline: 2.3946x; 2.3946x over previous
#include <cuda_runtime.h>
#include <cuda_bf16.h>
#include <math.h>
#include <stdint.h>

#define Bn  2
#define Tn  2048
#define Dn  1024
#define Hn  16
#define HDn 64
#define Mn  (Bn * Tn)   // 4096

// -------- scratch (static device globals; no allocations allowed) --------
__device__ __nv_bfloat162 g_xb[(size_t)Mn * Dn / 2];     // x in bf16
__device__ __nv_bfloat162 g_Wqb[(size_t)Dn * Dn / 2];
__device__ __nv_bfloat162 g_Wkb[(size_t)Dn * Dn / 2];
__device__ __nv_bfloat162 g_Wvb[(size_t)Dn * Dn / 2];
__device__ __nv_bfloat162 g_Wob[(size_t)Dn * Dn / 2];
__device__ unsigned g_Q[(size_t)Bn * Hn * Tn * HDn / 2]; // bf16x2 [bh*T+t][32]
__device__ unsigned g_K[(size_t)Bn * Hn * Tn * HDn / 2];
__device__ unsigned g_V[(size_t)Bn * Hn * Tn * HDn / 2];
__device__ unsigned g_O[(size_t)Mn * Dn / 2];            // bf16x2 [B*T][512]
__device__ float    g_P[(size_t)Mn * Dn];                // pre-LN fp32

// ---------------- helpers ----------------
__device__ __forceinline__ uint32_t s2u(const void* p) {
    return (uint32_t)__cvta_generic_to_shared(p);
}
__device__ __forceinline__ unsigned pk(float a, float b) {
    __nv_bfloat162 t = __float22bfloat162_rn(make_float2(a, b));
    return *(unsigned*)&t;
}
// D += A(16x16) * B(16x8), bf16 in, f32 accum
__device__ __forceinline__ void mma16(float* d, const unsigned* a,
                                      unsigned b0, unsigned b1) {
    asm volatile(
        "mma.sync.aligned.m16n8k16.row.col.f32.bf16.bf16.f32 "
        "{%0,%1,%2,%3},{%4,%5,%6,%7},{%8,%9},{%0,%1,%2,%3};"
        : "+f"(d[0]), "+f"(d[1]), "+f"(d[2]), "+f"(d[3])
        : "r"(a[0]), "r"(a[1]), "r"(a[2]), "r"(a[3]), "r"(b0), "r"(b1));
}
__device__ __forceinline__ void ldsm_x4(unsigned* r, uint32_t a) {
    asm volatile("ldmatrix.sync.aligned.m8n8.x4.shared.b16 {%0,%1,%2,%3}, [%4];"
        : "=r"(r[0]), "=r"(r[1]), "=r"(r[2]), "=r"(r[3]) : "r"(a));
}
__device__ __forceinline__ void ldsm_x4t(unsigned* r, uint32_t a) {
    asm volatile("ldmatrix.sync.aligned.m8n8.x4.trans.shared.b16 {%0,%1,%2,%3}, [%4];"
        : "=r"(r[0]), "=r"(r[1]), "=r"(r[2]), "=r"(r[3]) : "r"(a));
}
__device__ __forceinline__ void cpa16u(unsigned* dst, const void* src) {
    unsigned d = s2u(dst);
    asm volatile("cp.async.cg.shared.global [%0], [%1], 16;" :: "r"(d), "l"(src));
}
__device__ __forceinline__ void cp_commit() { asm volatile("cp.async.commit_group;"); }
template<int N> __device__ __forceinline__ void cp_wait() {
    asm volatile("cp.async.wait_group %0;" :: "n"(N));
}

// =========================================================================
// bf16 -> conversion pre-pass (x + 4 weights)
// =========================================================================
__global__ void __launch_bounds__(256) cvt_bf16(
    const float* __restrict__ x,
    const float* __restrict__ wq, const float* __restrict__ wk,
    const float* __restrict__ wv, const float* __restrict__ wo)
{
    const float* src; __nv_bfloat162* dst; int n4;
    switch (blockIdx.z) {
        case 0: src = x;  dst = g_xb;  n4 = Mn * Dn / 4; break;
        case 1: src = wq; dst = g_Wqb; n4 = Dn * Dn / 4; break;
        case 2: src = wk; dst = g_Wkb; n4 = Dn * Dn / 4; break;
        case 3: src = wv; dst = g_Wvb; n4 = Dn * Dn / 4; break;
        default: src = wo; dst = g_Wob; n4 = Dn * Dn / 4; break;
    }
    int i = blockIdx.x * 256 + threadIdx.x;
    if (i < n4) {
        float4 v = ((const float4*)src)[i];
        dst[2 * i]     = __float22bfloat162_rn(make_float2(v.x, v.y));
        dst[2 * i + 1] = __float22bfloat162_rn(make_float2(v.z, v.w));
    }
}

// =========================================================================
// bf16 tensor-core GEMM, 128x128 CTA tile, Kchunk=32, 3-stage cp.async.
// 256 threads = 8 warps (4m x 2n); warp 32m x 64n.
// A smem: [128 m][32 k bf16], row stride 80B. B smem: [32 k][128 n], 272B.
// =========================================================================
#define GA_U32 (128 * 20)            // 2560
#define GB_U32 (32 * 68)             // 2176
#define GST_U32 (GA_U32 + GB_U32)    // 4736
#define GEMM_SMEM_BYTES (3 * GST_U32 * 4)   // 56832

__device__ __forceinline__ void gemm_issue(
    unsigned* stage, const char* Ab, const char* Wb,
    int m0, int n0, int k0, int tid)
{
    unsigned* As = stage;
    unsigned* Bs = stage + GA_U32;
#pragma unroll
    for (int i = 0; i < 2; i++) {
        int s = tid + i * 256;
        int r = s >> 2, cw = s & 3;
        cpa16u(As + r * 20 + cw * 4, Ab + (size_t)(m0 + r) * 2048 + k0 * 2 + cw * 16);
        int rk = s >> 4, cn = s & 15;
        cpa16u(Bs + rk * 68 + cn * 4, Wb + (size_t)(k0 + rk) * 2048 + n0 * 2 + cn * 16);
    }
    cp_commit();
}

// mode 0: out_q = bf16x2 scatter to [bh*T+t][32], value scale applied
// mode 1: out_f = fp32 row-major + bias + resid
__device__ __forceinline__ void gemm_main(
    const char* Ab, const char* Wb,
    const float* __restrict__ bias, const float* __restrict__ resid,
    unsigned* out_q, float* out_f, int mode, float scale)
{
    extern __shared__ unsigned smu[];
    const int tid = threadIdx.x, lane = tid & 31, w = tid >> 5;
    const int g = lane >> 2, tig = lane & 3;
    const int wm = w & 3, wn = w >> 2;
    const int m0 = blockIdx.y * 128, n0 = blockIdx.x * 128;
    const int l15 = lane & 15, lhi = (lane >> 4) & 1;

    float acc[2][8][4];
#pragma unroll
    for (int mt = 0; mt < 2; mt++)
#pragma unroll
        for (int nt = 0; nt < 8; nt++)
#pragma unroll
            for (int j = 0; j < 4; j++) acc[mt][nt][j] = 0.f;

    gemm_issue(smu, Ab, Wb, m0, n0, 0, tid);
    gemm_issue(smu + GST_U32, Ab, Wb, m0, n0, 32, tid);
    gemm_issue(smu + 2 * GST_U32, Ab, Wb, m0, n0, 64, tid);

    for (int c = 0; c < 32; c++) {
        if (c < 30) cp_wait<2>(); else if (c == 30) cp_wait<1>(); else cp_wait<0>();
        __syncthreads();
        unsigned* As = smu + (c % 3) * GST_U32;
        unsigned* Bs = As + GA_U32;
        const uint32_t as_b = s2u(As), bs_b = s2u(Bs);

#pragma unroll
        for (int kk = 0; kk < 2; kk++) {
            unsigned av[2][4];
#pragma unroll
            for (int mt = 0; mt < 2; mt++)
                ldsm_x4(av[mt], as_b + (wm * 32 + mt * 16 + l15) * 80
                                     + (kk * 16 + lhi * 8) * 2);
#pragma unroll
            for (int ntp = 0; ntp < 4; ntp++) {
                unsigned bv[4];
                ldsm_x4t(bv, bs_b + (kk * 16 + l15) * 272
                                  + (wn * 64 + ntp * 16 + lhi * 8) * 2);
                mma16(acc[0][2 * ntp],     av[0], bv[0], bv[1]);
                mma16(acc[1][2 * ntp],     av[1], bv[0], bv[1]);
                mma16(acc[0][2 * ntp + 1], av[0], bv[2], bv[3]);
                mma16(acc[1][2 * ntp + 1], av[1], bv[2], bv[3]);
            }
        }
        __syncthreads();
        if (c + 3 < 32)
            gemm_issue(smu + (c % 3) * GST_U32, Ab, Wb, m0, n0, (c + 3) * 32, tid);
    }

    // epilogue
#pragma unroll
    for (int mt = 0; mt < 2; mt++) {
#pragma unroll
        for (int nt = 0; nt < 8; nt++) {
            int r0 = m0 + wm * 32 + mt * 16 + g;
            int n = n0 + wn * 64 + nt * 8 + 2 * tig;
            float bx = bias[n], by = bias[n + 1];
            if (mode == 0) {
#pragma unroll
                for (int rp = 0; rp < 2; rp++) {
                    int r = r0 + rp * 8;
                    int bb = r >> 11, t = r & (Tn - 1);
                    int h = n >> 6, hd = n & 63;
                    float v0 = (acc[mt][nt][2 * rp]     + bx) * scale;
                    float v1 = (acc[mt][nt][2 * rp + 1] + by) * scale;
                    out_q[(((size_t)(bb * Hn + h) * Tn + t) << 5) + (hd >> 1)] = pk(v0, v1);
                }
            } else {
#pragma unroll
                for (int rp = 0; rp < 2; rp++) {
                    int r = r0 + rp * 8;
                    size_t off = (size_t)r * Dn + n;
                    float2 rv = *(const float2*)&resid[off];
                    float2 val = make_float2(acc[mt][nt][2 * rp] + bx + rv.x,
                                             acc[mt][nt][2 * rp + 1] + by + rv.y);
                    *(float2*)&out_f[off] = val;
                }
            }
        }
    }
}

__global__ void __launch_bounds__(256, 2) qkv_gemm(
    const float* __restrict__ bq, const float* __restrict__ bk,
    const float* __restrict__ bv)
{
    const char* Wb; const float* b; unsigned* o; float scale;
    if (blockIdx.z == 0)      { Wb = (const char*)g_Wqb; b = bq; o = g_Q; scale = 0.125f; }
    else if (blockIdx.z == 1) { Wb = (const char*)g_Wkb; b = bk; o = g_K; scale = 1.f; }
    else                      { Wb = (const char*)g_Wvb; b = bv; o = g_V; scale = 1.f; }
    gemm_main((const char*)g_xb, Wb, b, nullptr, o, nullptr, 0, scale);
}

__global__ void __launch_bounds__(256, 2) oproj_gemm(
    const float* __restrict__ bo, const float* __restrict__ resid)
{
    gemm_main((const char*)g_O, (const char*)g_Wob, bo, resid,
              nullptr, g_P, 1, 1.f);
}

// =========================================================================
// bf16 flash attention. CTA = (bh, 128 query rows), 8 warps x 16 rows.
// K-tiles of 64, 3-stage cp.async. All smem rows 144B stride.
// smem: Q[128][72 bf16] (reused as P) | 3 stages x { K[64][72], V[64][72] }
// =========================================================================
#define AT_KV_U32 (64 * 36)           // 2304
#define AST_U32 (2 * AT_KV_U32)       // 4608
#define AQ_U32 (128 * 36)             // 4608
#define ATT_SMEM_BYTES ((AQ_U32 + 3 * AST_U32) * 4)   // 73728

__device__ __forceinline__ void attn_issue(
    unsigned* stage, const char* Kb, const char* Vb, int row0, int tid)
{
    unsigned* Ks = stage;
    unsigned* Vs = stage + AT_KV_U32;
#pragma unroll
    for (int i = 0; i < 2; i++) {
        int s = tid + i * 256;
        int r = s >> 3, cw = s & 7;
        cpa16u(Ks + r * 36 + cw * 4, Kb + (size_t)(row0 + r) * 128 + cw * 16);
        cpa16u(Vs + r * 36 + cw * 4, Vb + (size_t)(row0 + r) * 128 + cw * 16);
    }
    cp_commit();
}

__global__ void __launch_bounds__(256, 2) attn_tc(float* dummy)
{
    extern __shared__ unsigned smu[];
    unsigned* Qs = smu;            // reused as Ps
    unsigned* buf = smu + AQ_U32;

    const int tid = threadIdx.x, lane = tid & 31, w = tid >> 5;
    const int g = lane >> 2, tig = lane & 3;
    const int l15 = lane & 15, lhi = (lane >> 4) & 1, l8 = (lane >> 3) & 1;
    const int bh = blockIdx.y;
    const int q0 = blockIdx.x << 7;
    const int b = bh >> 4, h = bh & 15;
    const int rb = w * 16;

    const char* Qg = (const char*)g_Q + ((size_t)bh * Tn + q0) * 128;
    const char* Kg = (const char*)g_K + (size_t)bh * Tn * 128;
    const char* Vg = (const char*)g_V + (size_t)bh * Tn * 128;

    // group1: Q
#pragma unroll
    for (int i = 0; i < 4; i++) {
        int s = tid + i * 256;
        int r = s >> 3, cw = s & 7;
        cpa16u(Qs + r * 36 + cw * 4, Qg + (size_t)r * 128 + cw * 16);
    }
    cp_commit();
    attn_issue(buf,               Kg, Vg, 0,   tid);   // group2
    attn_issue(buf + AST_U32,     Kg, Vg, 64,  tid);   // group3
    attn_issue(buf + 2 * AST_U32, Kg, Vg, 128, tid);   // group4

    cp_wait<3>();
    __syncthreads();

    // Q fragments (Q pre-scaled by 1/8 at creation)
    const uint32_t qs_b = s2u(Qs);
    unsigned qa[4][4];
#pragma unroll
    for (int kk = 0; kk < 4; kk++)
        ldsm_x4(qa[kk], qs_b + (rb + l15) * 144 + (kk * 16 + lhi * 8) * 2);
    __syncthreads();                     // Qs now reusable as Ps
    unsigned* Ps = Qs;
    const uint32_t ps_b = qs_b;

    float oacc[8][4];
#pragma unroll
    for (int nt = 0; nt < 8; nt++)
#pragma unroll
        for (int j = 0; j < 4; j++) oacc[nt][j] = 0.f;
    float mst0 = -1e30f, mst1 = -1e30f, lst0 = 0.f, lst1 = 0.f;

    for (int it = 0; it < 32; it++) {
        if (it < 30) cp_wait<2>(); else if (it == 30) cp_wait<1>(); else cp_wait<0>();
        __syncthreads();
        unsigned* Ks = buf + (it % 3) * AST_U32;
        unsigned* Vs = Ks + AT_KV_U32;
        const uint32_t ks_b = s2u(Ks), vs_b = s2u(Vs);

        // ---- S = Q K^T ----
        float sacc[8][4];
#pragma unroll
        for (int nt = 0; nt < 8; nt++)
#pragma unroll
            for (int j = 0; j < 4; j++) sacc[nt][j] = 0.f;

#pragma unroll
        for (int kk = 0; kk < 4; kk++) {
#pragma unroll
            for (int ntp = 0; ntp < 4; ntp++) {
                unsigned kb[4];
                ldsm_x4(kb, ks_b + (ntp * 16 + (lane & 7) + lhi * 8) * 144
                                 + (kk * 16 + l8 * 8) * 2);
                mma16(sacc[2 * ntp],     qa[kk], kb[0], kb[1]);
                mma16(sacc[2 * ntp + 1], qa[kk], kb[2], kb[3]);
            }
        }

        // ---- online softmax (row quads: lanes xor 1,2) ----
        float mx0 = -1e30f, mx1 = -1e30f;
#pragma unroll
        for (int nt = 0; nt < 8; nt++) {
            mx0 = fmaxf(mx0, fmaxf(sacc[nt][0], sacc[nt][1]));
            mx1 = fmaxf(mx1, fmaxf(sacc[nt][2], sacc[nt][3]));
        }
        mx0 = fmaxf(mx0, __shfl_xor_sync(0xffffffffu, mx0, 1));
        mx0 = fmaxf(mx0, __shfl_xor_sync(0xffffffffu, mx0, 2));
        mx1 = fmaxf(mx1, __shfl_xor_sync(0xffffffffu, mx1, 1));
        mx1 = fmaxf(mx1, __shfl_xor_sync(0xffffffffu, mx1, 2));
        float mn0 = fmaxf(mst0, mx0), mn1 = fmaxf(mst1, mx1);
        float c0 = __expf(mst0 - mn0), c1 = __expf(mst1 - mn1);
        mst0 = mn0; mst1 = mn1;
        float s0 = 0.f, s1 = 0.f;
#pragma unroll
        for (int nt = 0; nt < 8; nt++) {
            float p0 = __expf(sacc[nt][0] - mn0);
            float p1 = __expf(sacc[nt][1] - mn0);
            float p2 = __expf(sacc[nt][2] - mn1);
            float p3 = __expf(sacc[nt][3] - mn1);
            s0 += p0 + p1; s1 += p2 + p3;
            sacc[nt][0] = p0; sacc[nt][1] = p1; sacc[nt][2] = p2; sacc[nt][3] = p3;
            oacc[nt][0] *= c0; oacc[nt][1] *= c0; oacc[nt][2] *= c1; oacc[nt][3] *= c1;
        }
        s0 += __shfl_xor_sync(0xffffffffu, s0, 1);
        s0 += __shfl_xor_sync(0xffffffffu, s0, 2);
        s1 += __shfl_xor_sync(0xffffffffu, s1, 1);
        s1 += __shfl_xor_sync(0xffffffffu, s1, 2);
        lst0 = lst0 * c0 + s0;
        lst1 = lst1 * c1 + s1;

        // ---- pack P (bf16x2 along keys), own warp rows ----
#pragma unroll
        for (int nt = 0; nt < 8; nt++) {
            Ps[(rb + g) * 36 + nt * 4 + tig]     = pk(sacc[nt][0], sacc[nt][1]);
            Ps[(rb + g + 8) * 36 + nt * 4 + tig] = pk(sacc[nt][2], sacc[nt][3]);
        }
        __syncwarp();

        // ---- O += P V ----
#pragma unroll
        for (int kk = 0; kk < 4; kk++) {
            unsigned pa[4];
            ldsm_x4(pa, ps_b + (rb + l15) * 144 + (kk * 16 + lhi * 8) * 2);
#pragma unroll
            for (int ntp = 0; ntp < 4; ntp++) {
                unsigned vb[4];
                ldsm_x4t(vb, vs_b + (kk * 16 + l15) * 144
                                  + (ntp * 16 + lhi * 8) * 2);
                mma16(oacc[2 * ntp],     pa, vb[0], vb[1]);
                mma16(oacc[2 * ntp + 1], pa, vb[2], vb[3]);
            }
        }
        __syncthreads();
        if (it + 3 < 32)
            attn_issue(buf + (it % 3) * AST_U32, Kg, Vg, (it + 3) * 64, tid);
    }

    // epilogue -> bf16 O [B*T][1024]
    float i0 = 1.f / lst0, i1 = 1.f / lst1;
    int gr0 = b * Tn + q0 + rb + g;
#pragma unroll
    for (int nt = 0; nt < 8; nt++) {
        int col = h * HDn + nt * 8 + 2 * tig;
        g_O[(size_t)gr0 * 512 + (col >> 1)] =
            pk(oacc[nt][0] * i0, oacc[nt][1] * i0);
        g_O[(size_t)(gr0 + 8) * 512 + (col >> 1)] =
            pk(oacc[nt][2] * i1, oacc[nt][3] * i1);
    }
    (void)dummy;
}

// =========================================================================
// LayerNorm: 1 block per row, 256 threads, 1 float4 per thread.
// =========================================================================
__global__ void __launch_bounds__(256) ln_kernel(
    const float* __restrict__ P, const float* __restrict__ gw,
    const float* __restrict__ gb, float* __restrict__ out)
{
    const int row = blockIdx.x;
    const int tid = threadIdx.x;
    const float4 v = ((const float4*)(P + (size_t)row * Dn))[tid];

    float s  = v.x + v.y + v.z + v.w;
    float ss = v.x * v.x + v.y * v.y + v.z * v.z + v.w * v.w;
#pragma unroll
    for (int off = 16; off; off >>= 1) {
        s  += __shfl_xor_sync(0xffffffffu, s, off);
        ss += __shfl_xor_sync(0xffffffffu, ss, off);
    }
    __shared__ float sh_s[8], sh_ss[8];
    const int w = tid >> 5, lane = tid & 31;
    if (lane == 0) { sh_s[w] = s; sh_ss[w] = ss; }
    __syncthreads();
    if (w == 0) {
        float s2  = (lane < 8) ? sh_s[lane]  : 0.f;
        float ss2 = (lane < 8) ? sh_ss[lane] : 0.f;
#pragma unroll
        for (int off = 4; off; off >>= 1) {
            s2  += __shfl_xor_sync(0xffffffffu, s2, off);
            ss2 += __shfl_xor_sync(0xffffffffu, ss2, off);
        }
        if (lane == 0) { sh_s[0] = s2; sh_ss[0] = ss2; }
    }
    __syncthreads();

    const float mu  = sh_s[0] * (1.0f / Dn);
    const float var = sh_ss[0] * (1.0f / Dn) - mu * mu;
    const float rs  = rsqrtf(var + 1e-5f);

    const float4 g = ((const float4*)gw)[tid];
    const float4 bb = ((const float4*)gb)[tid];
    float4 r;
    r.x = (v.x - mu) * rs * g.x + bb.x;
    r.y = (v.y - mu) * rs * g.y + bb.y;
    r.z = (v.z - mu) * rs * g.z + bb.z;
    r.w = (v.w - mu) * rs * g.w + bb.w;
    ((float4*)(out + (size_t)row * Dn))[tid] = r;
}

// =========================================================================
extern "C" void kernel_launch(void* const* d_in, const int* in_sizes, int n_in,
                              void* d_out, int out_size)
{
    const float* x  = (const float*)d_in[0];
    const float* Wq = (const float*)d_in[1];
    const float* bq = (const float*)d_in[2];
    const float* Wk = (const float*)d_in[3];
    const float* bk = (const float*)d_in[4];
    const float* Wv = (const float*)d_in[5];
    const float* bv = (const float*)d_in[6];
    const float* Wo = (const float*)d_in[7];
    const float* bo = (const float*)d_in[8];
    const float* lg = (const float*)d_in[9];
    const float* lb = (const float*)d_in[10];
    float* out = (float*)d_out;

    float* gP;
    cudaGetSymbolAddress((void**)&gP, g_P);

    cudaFuncSetAttribute(qkv_gemm, cudaFuncAttributeMaxDynamicSharedMemorySize,
                         GEMM_SMEM_BYTES);
    cudaFuncSetAttribute(oproj_gemm, cudaFuncAttributeMaxDynamicSharedMemorySize,
                         GEMM_SMEM_BYTES);
    cudaFuncSetAttribute(attn_tc, cudaFuncAttributeMaxDynamicSharedMemorySize,
                         ATT_SMEM_BYTES);

    cvt_bf16<<<dim3(4096, 1, 5), 256>>>(x, Wq, Wk, Wv, Wo);

    qkv_gemm<<<dim3(Dn / 128, Mn / 128, 3), 256, GEMM_SMEM_BYTES>>>(bq, bk, bv);

    attn_tc<<<dim3(Tn / 128, Bn * Hn), 256, ATT_SMEM_BYTES>>>(nullptr);

    oproj_gemm<<<dim3(Dn / 128, Mn / 128), 256, GEMM_SMEM_BYTES>>>(bo, x);

    ln_kernel<<<Mn, 256>>>(gP, lg, lb, out);
}

// round 7
// speedup vs baseline: 2.4356x; 1.0171x over previous
#include <cuda_runtime.h>
#include <cuda_bf16.h>
#include <math.h>
#include <stdint.h>

#define Bn  2
#define Tn  2048
#define Dn  1024
#define Hn  16
#define HDn 64
#define Mn  (Bn * Tn)   // 4096

// -------- scratch (static device globals; no allocations allowed) --------
__device__ __nv_bfloat162 g_xb[(size_t)Mn * Dn / 2];     // x in bf16
__device__ __nv_bfloat162 g_Wqb[(size_t)Dn * Dn / 2];
__device__ __nv_bfloat162 g_Wkb[(size_t)Dn * Dn / 2];
__device__ __nv_bfloat162 g_Wvb[(size_t)Dn * Dn / 2];
__device__ __nv_bfloat162 g_Wob[(size_t)Dn * Dn / 2];
__device__ unsigned g_Q[(size_t)Bn * Hn * Tn * HDn / 2]; // bf16x2 [bh*T+t][32]
__device__ unsigned g_K[(size_t)Bn * Hn * Tn * HDn / 2];
__device__ unsigned g_V[(size_t)Bn * Hn * Tn * HDn / 2];
__device__ unsigned g_O[(size_t)Mn * Dn / 2];            // bf16x2 [B*T][512]
__device__ float    g_P[(size_t)Mn * Dn];                // pre-LN fp32

// ---------------- helpers ----------------
__device__ __forceinline__ uint32_t s2u(const void* p) {
    return (uint32_t)__cvta_generic_to_shared(p);
}
__device__ __forceinline__ unsigned pk(float a, float b) {
    __nv_bfloat162 t = __float22bfloat162_rn(make_float2(a, b));
    return *(unsigned*)&t;
}
__device__ __forceinline__ float ex2(float x) {
    float y;
    asm("ex2.approx.f32 %0, %1;" : "=f"(y) : "f"(x));
    return y;
}
// D += A(16x16) * B(16x8), bf16 in, f32 accum
__device__ __forceinline__ void mma16(float* d, const unsigned* a,
                                      unsigned b0, unsigned b1) {
    asm volatile(
        "mma.sync.aligned.m16n8k16.row.col.f32.bf16.bf16.f32 "
        "{%0,%1,%2,%3},{%4,%5,%6,%7},{%8,%9},{%0,%1,%2,%3};"
        : "+f"(d[0]), "+f"(d[1]), "+f"(d[2]), "+f"(d[3])
        : "r"(a[0]), "r"(a[1]), "r"(a[2]), "r"(a[3]), "r"(b0), "r"(b1));
}
__device__ __forceinline__ void ldsm_x4(unsigned* r, uint32_t a) {
    asm volatile("ldmatrix.sync.aligned.m8n8.x4.shared.b16 {%0,%1,%2,%3}, [%4];"
        : "=r"(r[0]), "=r"(r[1]), "=r"(r[2]), "=r"(r[3]) : "r"(a));
}
__device__ __forceinline__ void ldsm_x4t(unsigned* r, uint32_t a) {
    asm volatile("ldmatrix.sync.aligned.m8n8.x4.trans.shared.b16 {%0,%1,%2,%3}, [%4];"
        : "=r"(r[0]), "=r"(r[1]), "=r"(r[2]), "=r"(r[3]) : "r"(a));
}
__device__ __forceinline__ void cpa16u(unsigned* dst, const void* src) {
    unsigned d = s2u(dst);
    asm volatile("cp.async.cg.shared.global [%0], [%1], 16;" :: "r"(d), "l"(src));
}
__device__ __forceinline__ void cp_commit() { asm volatile("cp.async.commit_group;"); }
template<int N> __device__ __forceinline__ void cp_wait() {
    asm volatile("cp.async.wait_group %0;" :: "n"(N));
}

// =========================================================================
// bf16 conversion pre-pass (x + 4 weights)
// =========================================================================
__global__ void __launch_bounds__(256) cvt_bf16(
    const float* __restrict__ x,
    const float* __restrict__ wq, const float* __restrict__ wk,
    const float* __restrict__ wv, const float* __restrict__ wo)
{
    const float* src; __nv_bfloat162* dst; int n4;
    switch (blockIdx.z) {
        case 0: src = x;  dst = g_xb;  n4 = Mn * Dn / 4; break;
        case 1: src = wq; dst = g_Wqb; n4 = Dn * Dn / 4; break;
        case 2: src = wk; dst = g_Wkb; n4 = Dn * Dn / 4; break;
        case 3: src = wv; dst = g_Wvb; n4 = Dn * Dn / 4; break;
        default: src = wo; dst = g_Wob; n4 = Dn * Dn / 4; break;
    }
    int i = blockIdx.x * 256 + threadIdx.x;
    if (i < n4) {
        float4 v = ((const float4*)src)[i];
        dst[2 * i]     = __float22bfloat162_rn(make_float2(v.x, v.y));
        dst[2 * i + 1] = __float22bfloat162_rn(make_float2(v.z, v.w));
    }
}

// =========================================================================
// bf16 tensor-core GEMM, 128x128 CTA tile, Kchunk=32, 3-stage cp.async,
// single barrier per chunk. 256 threads = 8 warps (4m x 2n).
// A smem: [128 m][32 k bf16], row stride 80B. B smem: [32 k][128 n], 272B.
// =========================================================================
#define GA_U32 (128 * 20)            // 2560
#define GB_U32 (32 * 68)             // 2176
#define GST_U32 (GA_U32 + GB_U32)    // 4736
#define GEMM_SMEM_BYTES (3 * GST_U32 * 4)   // 56832

__device__ __forceinline__ void gemm_issue(
    unsigned* stage, const char* Ab, const char* Wb,
    int m0, int n0, int k0, int tid)
{
    unsigned* As = stage;
    unsigned* Bs = stage + GA_U32;
#pragma unroll
    for (int i = 0; i < 2; i++) {
        int s = tid + i * 256;
        int r = s >> 2, cw = s & 3;
        cpa16u(As + r * 20 + cw * 4, Ab + (size_t)(m0 + r) * 2048 + k0 * 2 + cw * 16);
        int rk = s >> 4, cn = s & 15;
        cpa16u(Bs + rk * 68 + cn * 4, Wb + (size_t)(k0 + rk) * 2048 + n0 * 2 + cn * 16);
    }
    cp_commit();
}

// mode 0: out_q = bf16x2 scatter to [bh*T+t][32], value scale applied
// mode 1: out_f = fp32 row-major + bias + resid
__device__ __forceinline__ void gemm_main(
    const char* Ab, const char* Wb,
    const float* __restrict__ bias, const float* __restrict__ resid,
    unsigned* out_q, float* out_f, int mode, float scale)
{
    extern __shared__ unsigned smu[];
    const int tid = threadIdx.x, lane = tid & 31, w = tid >> 5;
    const int g = lane >> 2, tig = lane & 3;
    const int wm = w & 3, wn = w >> 2;
    const int m0 = blockIdx.y * 128, n0 = blockIdx.x * 128;
    const int l15 = lane & 15, lhi = (lane >> 4) & 1;

    float acc[2][8][4];
#pragma unroll
    for (int mt = 0; mt < 2; mt++)
#pragma unroll
        for (int nt = 0; nt < 8; nt++)
#pragma unroll
            for (int j = 0; j < 4; j++) acc[mt][nt][j] = 0.f;

    gemm_issue(smu, Ab, Wb, m0, n0, 0, tid);
    gemm_issue(smu + GST_U32, Ab, Wb, m0, n0, 32, tid);

    for (int c = 0; c < 32; c++) {
        if (c < 31) cp_wait<1>(); else cp_wait<0>();
        __syncthreads();
        // refill the slot consumed LAST iteration (safe: all warps passed barrier)
        if (c + 2 < 32)
            gemm_issue(smu + ((c + 2) % 3) * GST_U32, Ab, Wb, m0, n0, (c + 2) * 32, tid);

        unsigned* As = smu + (c % 3) * GST_U32;
        unsigned* Bs = As + GA_U32;
        const uint32_t as_b = s2u(As), bs_b = s2u(Bs);

#pragma unroll
        for (int kk = 0; kk < 2; kk++) {
            unsigned av[2][4];
#pragma unroll
            for (int mt = 0; mt < 2; mt++)
                ldsm_x4(av[mt], as_b + (wm * 32 + mt * 16 + l15) * 80
                                     + (kk * 16 + lhi * 8) * 2);
#pragma unroll
            for (int ntp = 0; ntp < 4; ntp++) {
                unsigned bv[4];
                ldsm_x4t(bv, bs_b + (kk * 16 + l15) * 272
                                  + (wn * 64 + ntp * 16 + lhi * 8) * 2);
                mma16(acc[0][2 * ntp],     av[0], bv[0], bv[1]);
                mma16(acc[1][2 * ntp],     av[1], bv[0], bv[1]);
                mma16(acc[0][2 * ntp + 1], av[0], bv[2], bv[3]);
                mma16(acc[1][2 * ntp + 1], av[1], bv[2], bv[3]);
            }
        }
    }

    // epilogue
#pragma unroll
    for (int mt = 0; mt < 2; mt++) {
#pragma unroll
        for (int nt = 0; nt < 8; nt++) {
            int r0 = m0 + wm * 32 + mt * 16 + g;
            int n = n0 + wn * 64 + nt * 8 + 2 * tig;
            float bx = bias[n], by = bias[n + 1];
            if (mode == 0) {
#pragma unroll
                for (int rp = 0; rp < 2; rp++) {
                    int r = r0 + rp * 8;
                    int bb = r >> 11, t = r & (Tn - 1);
                    int h = n >> 6, hd = n & 63;
                    float v0 = (acc[mt][nt][2 * rp]     + bx) * scale;
                    float v1 = (acc[mt][nt][2 * rp + 1] + by) * scale;
                    out_q[(((size_t)(bb * Hn + h) * Tn + t) << 5) + (hd >> 1)] = pk(v0, v1);
                }
            } else {
#pragma unroll
                for (int rp = 0; rp < 2; rp++) {
                    int r = r0 + rp * 8;
                    size_t off = (size_t)r * Dn + n;
                    float2 rv = *(const float2*)&resid[off];
                    float2 val = make_float2(acc[mt][nt][2 * rp] + bx + rv.x,
                                             acc[mt][nt][2 * rp + 1] + by + rv.y);
                    *(float2*)&out_f[off] = val;
                }
            }
        }
    }
}

// Q is scaled by (1/8)*log2(e) so softmax can run in exp2 domain.
#define QSCALE 0.18033688f

__global__ void __launch_bounds__(256, 2) qkv_gemm(
    const float* __restrict__ bq, const float* __restrict__ bk,
    const float* __restrict__ bv)
{
    const char* Wb; const float* b; unsigned* o; float scale;
    if (blockIdx.z == 0)      { Wb = (const char*)g_Wqb; b = bq; o = g_Q; scale = QSCALE; }
    else if (blockIdx.z == 1) { Wb = (const char*)g_Wkb; b = bk; o = g_K; scale = 1.f; }
    else                      { Wb = (const char*)g_Wvb; b = bv; o = g_V; scale = 1.f; }
    gemm_main((const char*)g_xb, Wb, b, nullptr, o, nullptr, 0, scale);
}

__global__ void __launch_bounds__(256, 2) oproj_gemm(
    const float* __restrict__ bo, const float* __restrict__ resid)
{
    gemm_main((const char*)g_O, (const char*)g_Wob, bo, resid,
              nullptr, g_P, 1, 1.f);
}

// =========================================================================
// bf16 flash attention. CTA = (bh, 128 query rows), 8 warps x 16 rows.
// K-tiles of 64, 3-stage cp.async, single barrier per tile.
// P never touches smem: S accumulator fragments are repacked directly into
// m16n8k16 A-operand fragments for P@V (identical register layout).
// Softmax in exp2 domain (Q pre-scaled by log2e/8).
// =========================================================================
#define AT_KV_U32 (64 * 36)           // 2304
#define AST_U32 (2 * AT_KV_U32)       // 4608
#define AQ_U32 (128 * 36)             // 4608
#define ATT_SMEM_BYTES ((AQ_U32 + 3 * AST_U32) * 4)   // 73728

__device__ __forceinline__ void attn_issue(
    unsigned* stage, const char* Kb, const char* Vb, int row0, int tid)
{
    unsigned* Ks = stage;
    unsigned* Vs = stage + AT_KV_U32;
#pragma unroll
    for (int i = 0; i < 2; i++) {
        int s = tid + i * 256;
        int r = s >> 3, cw = s & 7;
        cpa16u(Ks + r * 36 + cw * 4, Kb + (size_t)(row0 + r) * 128 + cw * 16);
        cpa16u(Vs + r * 36 + cw * 4, Vb + (size_t)(row0 + r) * 128 + cw * 16);
    }
    cp_commit();
}

__global__ void __launch_bounds__(256, 2) attn_tc(float* dummy)
{
    extern __shared__ unsigned smu[];
    unsigned* Qs = smu;
    unsigned* buf = smu + AQ_U32;

    const int tid = threadIdx.x, lane = tid & 31, w = tid >> 5;
    const int l15 = lane & 15, lhi = (lane >> 4) & 1, l8 = (lane >> 3) & 1;
    const int g = lane >> 2, tig = lane & 3;
    const int bh = blockIdx.y;
    const int q0 = blockIdx.x << 7;
    const int b = bh >> 4, h = bh & 15;
    const int rb = w * 16;

    const char* Qg = (const char*)g_Q + ((size_t)bh * Tn + q0) * 128;
    const char* Kg = (const char*)g_K + (size_t)bh * Tn * 128;
    const char* Vg = (const char*)g_V + (size_t)bh * Tn * 128;

    // group1: Q
#pragma unroll
    for (int i = 0; i < 4; i++) {
        int s = tid + i * 256;
        int r = s >> 3, cw = s & 7;
        cpa16u(Qs + r * 36 + cw * 4, Qg + (size_t)r * 128 + cw * 16);
    }
    cp_commit();
    attn_issue(buf,           Kg, Vg, 0,  tid);    // tile 0 -> slot 0
    attn_issue(buf + AST_U32, Kg, Vg, 64, tid);    // tile 1 -> slot 1

    cp_wait<2>();                // Q resident
    __syncthreads();

    // Q fragments (Q pre-scaled by log2e/8 at creation)
    const uint32_t qs_b = s2u(Qs);
    unsigned qa[4][4];
#pragma unroll
    for (int kk = 0; kk < 4; kk++)
        ldsm_x4(qa[kk], qs_b + (rb + l15) * 144 + (kk * 16 + lhi * 8) * 2);

    float oacc[8][4];
#pragma unroll
    for (int nt = 0; nt < 8; nt++)
#pragma unroll
        for (int j = 0; j < 4; j++) oacc[nt][j] = 0.f;
    float mst0 = -1e30f, mst1 = -1e30f, lst0 = 0.f, lst1 = 0.f;

    for (int it = 0; it < 32; it++) {
        if (it < 31) cp_wait<1>(); else cp_wait<0>();
        __syncthreads();
        // refill slot consumed last iteration
        if (it + 2 < 32)
            attn_issue(buf + ((it + 2) % 3) * AST_U32, Kg, Vg, (it + 2) * 64, tid);

        unsigned* Ks = buf + (it % 3) * AST_U32;
        unsigned* Vs = Ks + AT_KV_U32;
        const uint32_t ks_b = s2u(Ks), vs_b = s2u(Vs);

        // ---- S = Q K^T (exp2 domain) ----
        float sacc[8][4];
#pragma unroll
        for (int nt = 0; nt < 8; nt++)
#pragma unroll
            for (int j = 0; j < 4; j++) sacc[nt][j] = 0.f;

#pragma unroll
        for (int kk = 0; kk < 4; kk++) {
#pragma unroll
            for (int ntp = 0; ntp < 4; ntp++) {
                unsigned kb[4];
                ldsm_x4(kb, ks_b + (ntp * 16 + (lane & 7) + lhi * 8) * 144
                                 + (kk * 16 + l8 * 8) * 2);
                mma16(sacc[2 * ntp],     qa[kk], kb[0], kb[1]);
                mma16(sacc[2 * ntp + 1], qa[kk], kb[2], kb[3]);
            }
        }

        // ---- online softmax (row quads: lanes xor 1,2), base-2 ----
        float mx0 = -1e30f, mx1 = -1e30f;
#pragma unroll
        for (int nt = 0; nt < 8; nt++) {
            mx0 = fmaxf(mx0, fmaxf(sacc[nt][0], sacc[nt][1]));
            mx1 = fmaxf(mx1, fmaxf(sacc[nt][2], sacc[nt][3]));
        }
        mx0 = fmaxf(mx0, __shfl_xor_sync(0xffffffffu, mx0, 1));
        mx0 = fmaxf(mx0, __shfl_xor_sync(0xffffffffu, mx0, 2));
        mx1 = fmaxf(mx1, __shfl_xor_sync(0xffffffffu, mx1, 1));
        mx1 = fmaxf(mx1, __shfl_xor_sync(0xffffffffu, mx1, 2));
        float mn0 = fmaxf(mst0, mx0), mn1 = fmaxf(mst1, mx1);
        float c0 = ex2(mst0 - mn0), c1 = ex2(mst1 - mn1);
        mst0 = mn0; mst1 = mn1;
        float s0 = 0.f, s1 = 0.f;
#pragma unroll
        for (int nt = 0; nt < 8; nt++) {
            float p0 = ex2(sacc[nt][0] - mn0);
            float p1 = ex2(sacc[nt][1] - mn0);
            float p2 = ex2(sacc[nt][2] - mn1);
            float p3 = ex2(sacc[nt][3] - mn1);
            s0 += p0 + p1; s1 += p2 + p3;
            sacc[nt][0] = p0; sacc[nt][1] = p1; sacc[nt][2] = p2; sacc[nt][3] = p3;
            oacc[nt][0] *= c0; oacc[nt][1] *= c0; oacc[nt][2] *= c1; oacc[nt][3] *= c1;
        }
        s0 += __shfl_xor_sync(0xffffffffu, s0, 1);
        s0 += __shfl_xor_sync(0xffffffffu, s0, 2);
        s1 += __shfl_xor_sync(0xffffffffu, s1, 1);
        s1 += __shfl_xor_sync(0xffffffffu, s1, 2);
        lst0 = lst0 * c0 + s0;
        lst1 = lst1 * c1 + s1;

        // ---- O += P V : P fragments packed straight from S accumulators ----
#pragma unroll
        for (int kk = 0; kk < 4; kk++) {
            unsigned pa[4];
            pa[0] = pk(sacc[2 * kk][0],     sacc[2 * kk][1]);
            pa[1] = pk(sacc[2 * kk][2],     sacc[2 * kk][3]);
            pa[2] = pk(sacc[2 * kk + 1][0], sacc[2 * kk + 1][1]);
            pa[3] = pk(sacc[2 * kk + 1][2], sacc[2 * kk + 1][3]);
#pragma unroll
            for (int ntp = 0; ntp < 4; ntp++) {
                unsigned vb[4];
                ldsm_x4t(vb, vs_b + (kk * 16 + l15) * 144
                                  + (ntp * 16 + lhi * 8) * 2);
                mma16(oacc[2 * ntp],     pa, vb[0], vb[1]);
                mma16(oacc[2 * ntp + 1], pa, vb[2], vb[3]);
            }
        }
    }

    // epilogue -> bf16 O [B*T][1024]
    float i0 = 1.f / lst0, i1 = 1.f / lst1;
    int gr0 = b * Tn + q0 + rb + g;
#pragma unroll
    for (int nt = 0; nt < 8; nt++) {
        int col = h * HDn + nt * 8 + 2 * tig;
        g_O[(size_t)gr0 * 512 + (col >> 1)] =
            pk(oacc[nt][0] * i0, oacc[nt][1] * i0);
        g_O[(size_t)(gr0 + 8) * 512 + (col >> 1)] =
            pk(oacc[nt][2] * i1, oacc[nt][3] * i1);
    }
    (void)dummy;
}

// =========================================================================
// LayerNorm: 1 block per row, 256 threads, 1 float4 per thread.
// =========================================================================
__global__ void __launch_bounds__(256) ln_kernel(
    const float* __restrict__ P, const float* __restrict__ gw,
    const float* __restrict__ gb, float* __restrict__ out)
{
    const int row = blockIdx.x;
    const int tid = threadIdx.x;
    const float4 v = ((const float4*)(P + (size_t)row * Dn))[tid];

    float s  = v.x + v.y + v.z + v.w;
    float ss = v.x * v.x + v.y * v.y + v.z * v.z + v.w * v.w;
#pragma unroll
    for (int off = 16; off; off >>= 1) {
        s  += __shfl_xor_sync(0xffffffffu, s, off);
        ss += __shfl_xor_sync(0xffffffffu, ss, off);
    }
    __shared__ float sh_s[8], sh_ss[8];
    const int w = tid >> 5, lane = tid & 31;
    if (lane == 0) { sh_s[w] = s; sh_ss[w] = ss; }
    __syncthreads();
    if (w == 0) {
        float s2  = (lane < 8) ? sh_s[lane]  : 0.f;
        float ss2 = (lane < 8) ? sh_ss[lane] : 0.f;
#pragma unroll
        for (int off = 4; off; off >>= 1) {
            s2  += __shfl_xor_sync(0xffffffffu, s2, off);
            ss2 += __shfl_xor_sync(0xffffffffu, ss2, off);
        }
        if (lane == 0) { sh_s[0] = s2; sh_ss[0] = ss2; }
    }
    __syncthreads();

    const float mu  = sh_s[0] * (1.0f / Dn);
    const float var = sh_ss[0] * (1.0f / Dn) - mu * mu;
    const float rs  = rsqrtf(var + 1e-5f);

    const float4 g = ((const float4*)gw)[tid];
    const float4 bb = ((const float4*)gb)[tid];
    float4 r;
    r.x = (v.x - mu) * rs * g.x + bb.x;
    r.y = (v.y - mu) * rs * g.y + bb.y;
    r.z = (v.z - mu) * rs * g.z + bb.z;
    r.w = (v.w - mu) * rs * g.w + bb.w;
    ((float4*)(out + (size_t)row * Dn))[tid] = r;
}

// =========================================================================
extern "C" void kernel_launch(void* const* d_in, const int* in_sizes, int n_in,
                              void* d_out, int out_size)
{
    const float* x  = (const float*)d_in[0];
    const float* Wq = (const float*)d_in[1];
    const float* bq = (const float*)d_in[2];
    const float* Wk = (const float*)d_in[3];
    const float* bk = (const float*)d_in[4];
    const float* Wv = (const float*)d_in[5];
    const float* bv = (const float*)d_in[6];
    const float* Wo = (const float*)d_in[7];
    const float* bo = (const float*)d_in[8];
    const float* lg = (const float*)d_in[9];
    const float* lb = (const float*)d_in[10];
    float* out = (float*)d_out;

    float* gP;
    cudaGetSymbolAddress((void**)&gP, g_P);

    cudaFuncSetAttribute(qkv_gemm, cudaFuncAttributeMaxDynamicSharedMemorySize,
                         GEMM_SMEM_BYTES);
    cudaFuncSetAttribute(oproj_gemm, cudaFuncAttributeMaxDynamicSharedMemorySize,
                         GEMM_SMEM_BYTES);
    cudaFuncSetAttribute(attn_tc, cudaFuncAttributeMaxDynamicSharedMemorySize,
                         ATT_SMEM_BYTES);

    cvt_bf16<<<dim3(4096, 1, 5), 256>>>(x, Wq, Wk, Wv, Wo);

    qkv_gemm<<<dim3(Dn / 128, Mn / 128, 3), 256, GEMM_SMEM_BYTES>>>(bq, bk, bv);

    attn_tc<<<dim3(Tn / 128, Bn * Hn), 256, ATT_SMEM_BYTES>>>(nullptr);

    oproj_gemm<<<dim3(Dn / 128, Mn / 128), 256, GEMM_SMEM_BYTES>>>(bo, x);

    ln_kernel<<<Mn, 256>>>(gP, lg, lb, out);
}

// round 8
// speedup vs baseline: 2.7037x; 1.1101x over previous
#include <cuda_runtime.h>
#include <cuda.h>
#include <cuda_bf16.h>
#include <math.h>
#include <stdint.h>

#define Bn  2
#define Tn  2048
#define Dn  1024
#define Hn  16
#define HDn 64
#define Mn  (Bn * Tn)   // 4096

// -------- scratch (static device globals; no allocations allowed) --------
__device__ __nv_bfloat162 g_xb[(size_t)Mn * Dn / 2];     // x bf16 [4096][1024]
__device__ __nv_bfloat162 g_Wqb[(size_t)Dn * Dn / 2];    // W bf16 [k][n]
__device__ __nv_bfloat162 g_Wkb[(size_t)Dn * Dn / 2];
__device__ __nv_bfloat162 g_Wvb[(size_t)Dn * Dn / 2];
__device__ __nv_bfloat162 g_Wob[(size_t)Dn * Dn / 2];
__device__ unsigned g_Q[(size_t)Bn * Hn * Tn * HDn / 2]; // bf16x2 [bh*T+t][32]
__device__ unsigned g_K[(size_t)Bn * Hn * Tn * HDn / 2];
__device__ unsigned g_V[(size_t)Bn * Hn * Tn * HDn / 2];
__device__ unsigned g_O[(size_t)Mn * Dn / 2];            // bf16x2 [B*T][512]
__device__ float    g_P[(size_t)Mn * Dn];                // pre-LN fp32

// ---------------- helpers ----------------
__device__ __forceinline__ uint32_t s2u(const void* p) {
    return (uint32_t)__cvta_generic_to_shared(p);
}
__device__ __forceinline__ unsigned pk(float a, float b) {
    __nv_bfloat162 t = __float22bfloat162_rn(make_float2(a, b));
    return *(unsigned*)&t;
}
__device__ __forceinline__ float ex2(float x) {
    float y;
    asm("ex2.approx.f32 %0, %1;" : "=f"(y) : "f"(x));
    return y;
}
// SW128 swizzle on byte offset within a tile of 128B rows
__device__ __forceinline__ uint32_t swz(uint32_t o) {
    return o ^ ((o >> 3) & 0x70);
}
__device__ __forceinline__ void mma16(float* d, const unsigned* a,
                                      unsigned b0, unsigned b1) {
    asm volatile(
        "mma.sync.aligned.m16n8k16.row.col.f32.bf16.bf16.f32 "
        "{%0,%1,%2,%3},{%4,%5,%6,%7},{%8,%9},{%0,%1,%2,%3};"
        : "+f"(d[0]), "+f"(d[1]), "+f"(d[2]), "+f"(d[3])
        : "r"(a[0]), "r"(a[1]), "r"(a[2]), "r"(a[3]), "r"(b0), "r"(b1));
}
__device__ __forceinline__ void ldsm_x4(unsigned* r, uint32_t a) {
    asm volatile("ldmatrix.sync.aligned.m8n8.x4.shared.b16 {%0,%1,%2,%3}, [%4];"
        : "=r"(r[0]), "=r"(r[1]), "=r"(r[2]), "=r"(r[3]) : "r"(a));
}
__device__ __forceinline__ void ldsm_x4t(unsigned* r, uint32_t a) {
    asm volatile("ldmatrix.sync.aligned.m8n8.x4.trans.shared.b16 {%0,%1,%2,%3}, [%4];"
        : "=r"(r[0]), "=r"(r[1]), "=r"(r[2]), "=r"(r[3]) : "r"(a));
}
__device__ __forceinline__ void mbar_init(uint32_t m, uint32_t cnt) {
    asm volatile("mbarrier.init.shared.b64 [%0], %1;" :: "r"(m), "r"(cnt) : "memory");
}
__device__ __forceinline__ void mbar_expect(uint32_t m, uint32_t bytes) {
    asm volatile("mbarrier.arrive.expect_tx.shared.b64 _, [%0], %1;"
                 :: "r"(m), "r"(bytes) : "memory");
}
__device__ __forceinline__ void mbar_wait(uint32_t m, uint32_t parity) {
    asm volatile(
        "{\n\t.reg .pred P1;\n\t"
        "WAIT_%=:\n\t"
        "mbarrier.try_wait.parity.acquire.cta.shared::cta.b64 P1, [%0], %1, 0x989680;\n\t"
        "@P1 bra.uni DONE_%=;\n\t"
        "bra.uni WAIT_%=;\n\t"
        "DONE_%=:\n\t}"
        :: "r"(m), "r"(parity) : "memory");
}
__device__ __forceinline__ void tma2d(uint32_t dst, const CUtensorMap* tm,
                                      int x, int y, uint32_t mbar) {
    asm volatile(
        "cp.async.bulk.tensor.2d.shared::cta.global.tile.mbarrier::complete_tx::bytes "
        "[%0], [%1, {%2, %3}], [%4];"
        :: "r"(dst), "l"(tm), "r"(x), "r"(y), "r"(mbar) : "memory");
}

// =========================================================================
// bf16 conversion pre-pass (x + 4 weights)
// =========================================================================
__global__ void __launch_bounds__(256) cvt_bf16(
    const float* __restrict__ x,
    const float* __restrict__ wq, const float* __restrict__ wk,
    const float* __restrict__ wv, const float* __restrict__ wo)
{
    const float* src; __nv_bfloat162* dst; int n4;
    switch (blockIdx.z) {
        case 0: src = x;  dst = g_xb;  n4 = Mn * Dn / 4; break;
        case 1: src = wq; dst = g_Wqb; n4 = Dn * Dn / 4; break;
        case 2: src = wk; dst = g_Wkb; n4 = Dn * Dn / 4; break;
        case 3: src = wv; dst = g_Wvb; n4 = Dn * Dn / 4; break;
        default: src = wo; dst = g_Wob; n4 = Dn * Dn / 4; break;
    }
    int i = blockIdx.x * 256 + threadIdx.x;
    if (i < n4) {
        float4 v = ((const float4*)src)[i];
        dst[2 * i]     = __float22bfloat162_rn(make_float2(v.x, v.y));
        dst[2 * i + 1] = __float22bfloat162_rn(make_float2(v.z, v.w));
    }
}

// =========================================================================
// bf16 GEMM, 128x128 CTA tile, K-chunk 64, 3-stage TMA pipeline.
// 256 threads = 8 warps (4m x 2n). Stage 32KB:
//   A [128 m][64 k] SW128 (16KB) | B 2 subtiles [64 k][64 n] SW128 (8KB each)
// Loads: thread 0 issues 3 UTMALDG per stage; everyone waits mbar parity.
// =========================================================================
#define G_STG 32768
#define GEMM_DSMEM (3 * G_STG + 1024)

__device__ __forceinline__ void gemm_main(
    const CUtensorMap* tmA, const CUtensorMap* tmB,
    const float* __restrict__ bias, const float* __restrict__ resid,
    unsigned* out_q, float* out_f, int mode, float scale)
{
    extern __shared__ char smraw[];
    char* smb = (char*)(((uintptr_t)smraw + 1023) & ~(uintptr_t)1023);
    __shared__ uint64_t mb[3];

    const int tid = threadIdx.x, lane = tid & 31, w = tid >> 5;
    const int g = lane >> 2, tig = lane & 3;
    const int wm = w & 3, wn = w >> 2;
    const int l15 = lane & 15, lhi = (lane >> 4) & 1;
    const int m0 = blockIdx.y * 128, n0 = blockIdx.x * 128;
    const uint32_t smu = s2u(smb);

    if (tid == 0)
        for (int s = 0; s < 3; s++) mbar_init(s2u(&mb[s]), 1);
    __syncthreads();
    if (tid == 0) {
        for (int s = 0; s < 2; s++) {       // chunks 0,1 -> slots 0,1
            uint32_t st = smu + s * G_STG;
            mbar_expect(s2u(&mb[s]), G_STG);
            tma2d(st,          tmA, s * 64,  m0,     s2u(&mb[s]));
            tma2d(st + 16384,  tmB, n0,      s * 64, s2u(&mb[s]));
            tma2d(st + 24576,  tmB, n0 + 64, s * 64, s2u(&mb[s]));
        }
    }

    float acc[2][8][4];
#pragma unroll
    for (int mt = 0; mt < 2; mt++)
#pragma unroll
        for (int nt = 0; nt < 8; nt++)
#pragma unroll
            for (int j = 0; j < 4; j++) acc[mt][nt][j] = 0.f;

    for (int c = 0; c < 16; c++) {
        mbar_wait(s2u(&mb[c % 3]), (c / 3) & 1);
        __syncthreads();                    // all warps done with slot (c-1)%3
        if (tid == 0 && c + 2 < 16) {
            int s = (c + 2) % 3;
            uint32_t st = smu + s * G_STG;
            mbar_expect(s2u(&mb[s]), G_STG);
            tma2d(st,          tmA, (c + 2) * 64, m0,           s2u(&mb[s]));
            tma2d(st + 16384,  tmB, n0,           (c + 2) * 64, s2u(&mb[s]));
            tma2d(st + 24576,  tmB, n0 + 64,      (c + 2) * 64, s2u(&mb[s]));
        }

        const uint32_t as_b = smu + (c % 3) * G_STG;
        const uint32_t bs_b = as_b + 16384 + wn * 8192;

#pragma unroll
        for (int kk = 0; kk < 4; kk++) {
            unsigned av[2][4];
#pragma unroll
            for (int mt = 0; mt < 2; mt++)
                ldsm_x4(av[mt], as_b + swz((wm * 32 + mt * 16 + l15) * 128
                                           + (kk * 16 + lhi * 8) * 2));
#pragma unroll
            for (int ntp = 0; ntp < 4; ntp++) {
                unsigned bv[4];
                ldsm_x4t(bv, bs_b + swz((kk * 16 + l15) * 128
                                        + (ntp * 16 + lhi * 8) * 2));
                mma16(acc[0][2 * ntp],     av[0], bv[0], bv[1]);
                mma16(acc[1][2 * ntp],     av[1], bv[0], bv[1]);
                mma16(acc[0][2 * ntp + 1], av[0], bv[2], bv[3]);
                mma16(acc[1][2 * ntp + 1], av[1], bv[2], bv[3]);
            }
        }
    }

    // epilogue
#pragma unroll
    for (int mt = 0; mt < 2; mt++) {
#pragma unroll
        for (int nt = 0; nt < 8; nt++) {
            int r0 = m0 + wm * 32 + mt * 16 + g;
            int n = n0 + wn * 64 + nt * 8 + 2 * tig;
            float bx = bias[n], by = bias[n + 1];
            if (mode == 0) {
#pragma unroll
                for (int rp = 0; rp < 2; rp++) {
                    int r = r0 + rp * 8;
                    int bb = r >> 11, t = r & (Tn - 1);
                    int h = n >> 6, hd = n & 63;
                    float v0 = (acc[mt][nt][2 * rp]     + bx) * scale;
                    float v1 = (acc[mt][nt][2 * rp + 1] + by) * scale;
                    out_q[(((size_t)(bb * Hn + h) * Tn + t) << 5) + (hd >> 1)] = pk(v0, v1);
                }
            } else {
#pragma unroll
                for (int rp = 0; rp < 2; rp++) {
                    int r = r0 + rp * 8;
                    size_t off = (size_t)r * Dn + n;
                    float2 rv = *(const float2*)&resid[off];
                    float2 val = make_float2(acc[mt][nt][2 * rp] + bx + rv.x,
                                             acc[mt][nt][2 * rp + 1] + by + rv.y);
                    *(float2*)&out_f[off] = val;
                }
            }
        }
    }
}

// Q is scaled by (1/8)*log2(e) so softmax can run in exp2 domain.
#define QSCALE 0.18033688f

__global__ void __launch_bounds__(256, 2) qkv_gemm(
    const __grid_constant__ CUtensorMap tmA,
    const __grid_constant__ CUtensorMap tmq,
    const __grid_constant__ CUtensorMap tmk,
    const __grid_constant__ CUtensorMap tmv,
    const float* __restrict__ bq, const float* __restrict__ bk,
    const float* __restrict__ bv)
{
    const CUtensorMap* tb; const float* b; unsigned* o; float scale;
    if (blockIdx.z == 0)      { tb = &tmq; b = bq; o = g_Q; scale = QSCALE; }
    else if (blockIdx.z == 1) { tb = &tmk; b = bk; o = g_K; scale = 1.f; }
    else                      { tb = &tmv; b = bv; o = g_V; scale = 1.f; }
    gemm_main(&tmA, tb, b, nullptr, o, nullptr, 0, scale);
}

__global__ void __launch_bounds__(256, 2) oproj_gemm(
    const __grid_constant__ CUtensorMap tmA,
    const __grid_constant__ CUtensorMap tmW,
    const float* __restrict__ bo, const float* __restrict__ resid)
{
    gemm_main(&tmA, &tmW, bo, resid, nullptr, g_P, 1, 1.f);
}

// =========================================================================
// bf16 flash attention, TMA loads. CTA = (bh, 128 query rows), 8 warps.
// K-tiles of 64, 3-stage pipeline. smem: Q[128][64] SW128 (16KB) |
// 3 stages x { K[64][64] SW128 8KB, V[64][64] SW128 8KB }.
// P stays in registers (S-accum -> A-fragment repack); softmax in exp2.
// =========================================================================
#define A_STG 16384
#define ATT_DSMEM (16384 + 3 * A_STG + 1024)

__global__ void __launch_bounds__(256, 2) attn_tc(
    const __grid_constant__ CUtensorMap tmQ,
    const __grid_constant__ CUtensorMap tmK,
    const __grid_constant__ CUtensorMap tmV)
{
    extern __shared__ char smraw[];
    char* smb = (char*)(((uintptr_t)smraw + 1023) & ~(uintptr_t)1023);
    __shared__ uint64_t mbq, mb[3];

    const int tid = threadIdx.x, lane = tid & 31, w = tid >> 5;
    const int l15 = lane & 15, lhi = (lane >> 4) & 1, l8 = (lane >> 3) & 1;
    const int g = lane >> 2, tig = lane & 3;
    const int bh = blockIdx.y;
    const int q0 = blockIdx.x << 7;
    const int b = bh >> 4, h = bh & 15;
    const int rb = w * 16;
    const int krow0 = bh * Tn;
    const uint32_t smu = s2u(smb);
    const uint32_t qs_b = smu, buf = smu + 16384;

    if (tid == 0) {
        mbar_init(s2u(&mbq), 1);
        for (int s = 0; s < 3; s++) mbar_init(s2u(&mb[s]), 1);
    }
    __syncthreads();
    if (tid == 0) {
        mbar_expect(s2u(&mbq), 16384);
        tma2d(qs_b, &tmQ, 0, krow0 + q0, s2u(&mbq));
        for (int s = 0; s < 2; s++) {
            uint32_t st = buf + s * A_STG;
            mbar_expect(s2u(&mb[s]), A_STG);
            tma2d(st,        &tmK, 0, krow0 + s * 64, s2u(&mb[s]));
            tma2d(st + 8192, &tmV, 0, krow0 + s * 64, s2u(&mb[s]));
        }
    }

    // Q fragments (Q pre-scaled by log2e/8 at creation)
    mbar_wait(s2u(&mbq), 0);
    unsigned qa[4][4];
#pragma unroll
    for (int kk = 0; kk < 4; kk++)
        ldsm_x4(qa[kk], qs_b + swz((rb + l15) * 128 + (kk * 16 + lhi * 8) * 2));

    float oacc[8][4];
#pragma unroll
    for (int nt = 0; nt < 8; nt++)
#pragma unroll
        for (int j = 0; j < 4; j++) oacc[nt][j] = 0.f;
    float mst0 = -1e30f, mst1 = -1e30f, lst0 = 0.f, lst1 = 0.f;

    for (int it = 0; it < 32; it++) {
        mbar_wait(s2u(&mb[it % 3]), (it / 3) & 1);
        __syncthreads();                      // slot (it-1)%3 fully consumed
        if (tid == 0 && it + 2 < 32) {
            int s = (it + 2) % 3;
            uint32_t st = buf + s * A_STG;
            mbar_expect(s2u(&mb[s]), A_STG);
            tma2d(st,        &tmK, 0, krow0 + (it + 2) * 64, s2u(&mb[s]));
            tma2d(st + 8192, &tmV, 0, krow0 + (it + 2) * 64, s2u(&mb[s]));
        }

        const uint32_t ks_b = buf + (it % 3) * A_STG;
        const uint32_t vs_b = ks_b + 8192;

        // ---- S = Q K^T (exp2 domain) ----
        float sacc[8][4];
#pragma unroll
        for (int nt = 0; nt < 8; nt++)
#pragma unroll
            for (int j = 0; j < 4; j++) sacc[nt][j] = 0.f;

#pragma unroll
        for (int kk = 0; kk < 4; kk++) {
#pragma unroll
            for (int ntp = 0; ntp < 4; ntp++) {
                unsigned kb[4];
                ldsm_x4(kb, ks_b + swz((ntp * 16 + (lane & 7) + lhi * 8) * 128
                                       + (kk * 16 + l8 * 8) * 2));
                mma16(sacc[2 * ntp],     qa[kk], kb[0], kb[1]);
                mma16(sacc[2 * ntp + 1], qa[kk], kb[2], kb[3]);
            }
        }

        // ---- online softmax (row quads: lanes xor 1,2), base-2 ----
        float mx0 = -1e30f, mx1 = -1e30f;
#pragma unroll
        for (int nt = 0; nt < 8; nt++) {
            mx0 = fmaxf(mx0, fmaxf(sacc[nt][0], sacc[nt][1]));
            mx1 = fmaxf(mx1, fmaxf(sacc[nt][2], sacc[nt][3]));
        }
        mx0 = fmaxf(mx0, __shfl_xor_sync(0xffffffffu, mx0, 1));
        mx0 = fmaxf(mx0, __shfl_xor_sync(0xffffffffu, mx0, 2));
        mx1 = fmaxf(mx1, __shfl_xor_sync(0xffffffffu, mx1, 1));
        mx1 = fmaxf(mx1, __shfl_xor_sync(0xffffffffu, mx1, 2));
        float mn0 = fmaxf(mst0, mx0), mn1 = fmaxf(mst1, mx1);
        float c0 = ex2(mst0 - mn0), c1 = ex2(mst1 - mn1);
        mst0 = mn0; mst1 = mn1;
        float s0 = 0.f, s1 = 0.f;
#pragma unroll
        for (int nt = 0; nt < 8; nt++) {
            float p0 = ex2(sacc[nt][0] - mn0);
            float p1 = ex2(sacc[nt][1] - mn0);
            float p2 = ex2(sacc[nt][2] - mn1);
            float p3 = ex2(sacc[nt][3] - mn1);
            s0 += p0 + p1; s1 += p2 + p3;
            sacc[nt][0] = p0; sacc[nt][1] = p1; sacc[nt][2] = p2; sacc[nt][3] = p3;
            oacc[nt][0] *= c0; oacc[nt][1] *= c0; oacc[nt][2] *= c1; oacc[nt][3] *= c1;
        }
        s0 += __shfl_xor_sync(0xffffffffu, s0, 1);
        s0 += __shfl_xor_sync(0xffffffffu, s0, 2);
        s1 += __shfl_xor_sync(0xffffffffu, s1, 1);
        s1 += __shfl_xor_sync(0xffffffffu, s1, 2);
        lst0 = lst0 * c0 + s0;
        lst1 = lst1 * c1 + s1;

        // ---- O += P V : P fragments packed straight from S accumulators ----
#pragma unroll
        for (int kk = 0; kk < 4; kk++) {
            unsigned pa[4];
            pa[0] = pk(sacc[2 * kk][0],     sacc[2 * kk][1]);
            pa[1] = pk(sacc[2 * kk][2],     sacc[2 * kk][3]);
            pa[2] = pk(sacc[2 * kk + 1][0], sacc[2 * kk + 1][1]);
            pa[3] = pk(sacc[2 * kk + 1][2], sacc[2 * kk + 1][3]);
#pragma unroll
            for (int ntp = 0; ntp < 4; ntp++) {
                unsigned vb[4];
                ldsm_x4t(vb, vs_b + swz((kk * 16 + l15) * 128
                                        + (ntp * 16 + lhi * 8) * 2));
                mma16(oacc[2 * ntp],     pa, vb[0], vb[1]);
                mma16(oacc[2 * ntp + 1], pa, vb[2], vb[3]);
            }
        }
    }

    // epilogue -> bf16 O [B*T][1024]
    float i0 = 1.f / lst0, i1 = 1.f / lst1;
    int gr0 = b * Tn + q0 + rb + g;
#pragma unroll
    for (int nt = 0; nt < 8; nt++) {
        int col = h * HDn + nt * 8 + 2 * tig;
        g_O[(size_t)gr0 * 512 + (col >> 1)] =
            pk(oacc[nt][0] * i0, oacc[nt][1] * i0);
        g_O[(size_t)(gr0 + 8) * 512 + (col >> 1)] =
            pk(oacc[nt][2] * i1, oacc[nt][3] * i1);
    }
}

// =========================================================================
// LayerNorm: 1 block per row, 256 threads, 1 float4 per thread.
// =========================================================================
__global__ void __launch_bounds__(256) ln_kernel(
    const float* __restrict__ P, const float* __restrict__ gw,
    const float* __restrict__ gb, float* __restrict__ out)
{
    const int row = blockIdx.x;
    const int tid = threadIdx.x;
    const float4 v = ((const float4*)(P + (size_t)row * Dn))[tid];

    float s  = v.x + v.y + v.z + v.w;
    float ss = v.x * v.x + v.y * v.y + v.z * v.z + v.w * v.w;
#pragma unroll
    for (int off = 16; off; off >>= 1) {
        s  += __shfl_xor_sync(0xffffffffu, s, off);
        ss += __shfl_xor_sync(0xffffffffu, ss, off);
    }
    __shared__ float sh_s[8], sh_ss[8];
    const int w = tid >> 5, lane = tid & 31;
    if (lane == 0) { sh_s[w] = s; sh_ss[w] = ss; }
    __syncthreads();
    if (w == 0) {
        float s2  = (lane < 8) ? sh_s[lane]  : 0.f;
        float ss2 = (lane < 8) ? sh_ss[lane] : 0.f;
#pragma unroll
        for (int off = 4; off; off >>= 1) {
            s2  += __shfl_xor_sync(0xffffffffu, s2, off);
            ss2 += __shfl_xor_sync(0xffffffffu, ss2, off);
        }
        if (lane == 0) { sh_s[0] = s2; sh_ss[0] = ss2; }
    }
    __syncthreads();

    const float mu  = sh_s[0] * (1.0f / Dn);
    const float var = sh_ss[0] * (1.0f / Dn) - mu * mu;
    const float rs  = rsqrtf(var + 1e-5f);

    const float4 g = ((const float4*)gw)[tid];
    const float4 bb = ((const float4*)gb)[tid];
    float4 r;
    r.x = (v.x - mu) * rs * g.x + bb.x;
    r.y = (v.y - mu) * rs * g.y + bb.y;
    r.z = (v.z - mu) * rs * g.z + bb.z;
    r.w = (v.w - mu) * rs * g.w + bb.w;
    ((float4*)(out + (size_t)row * Dn))[tid] = r;
}

// =========================================================================
// Host
// =========================================================================
typedef CUresult (*PFN_tmencode)(
    CUtensorMap*, CUtensorMapDataType, cuuint32_t, void*,
    const cuuint64_t*, const cuuint64_t*, const cuuint32_t*, const cuuint32_t*,
    CUtensorMapInterleave, CUtensorMapSwizzle, CUtensorMapL2promotion,
    CUtensorMapFloatOOBfill);

static void mkmap_bf16(PFN_tmencode enc, CUtensorMap* tm, const void* ptr,
                       unsigned long long d0, unsigned long long d1,
                       unsigned long long stride_bytes, unsigned b0, unsigned b1)
{
    cuuint64_t dims[2] = {(cuuint64_t)d0, (cuuint64_t)d1};
    cuuint64_t str[1]  = {(cuuint64_t)stride_bytes};
    cuuint32_t box[2]  = {b0, b1};
    cuuint32_t es[2]   = {1, 1};
    enc(tm, CU_TENSOR_MAP_DATA_TYPE_BFLOAT16, 2, (void*)ptr, dims, str, box, es,
        CU_TENSOR_MAP_INTERLEAVE_NONE, CU_TENSOR_MAP_SWIZZLE_128B,
        CU_TENSOR_MAP_L2_PROMOTION_L2_128B, CU_TENSOR_MAP_FLOAT_OOB_FILL_NONE);
}

extern "C" void kernel_launch(void* const* d_in, const int* in_sizes, int n_in,
                              void* d_out, int out_size)
{
    const float* x  = (const float*)d_in[0];
    const float* Wq = (const float*)d_in[1];
    const float* bq = (const float*)d_in[2];
    const float* Wk = (const float*)d_in[3];
    const float* bk = (const float*)d_in[4];
    const float* Wv = (const float*)d_in[5];
    const float* bv = (const float*)d_in[6];
    const float* Wo = (const float*)d_in[7];
    const float* bo = (const float*)d_in[8];
    const float* lg = (const float*)d_in[9];
    const float* lb = (const float*)d_in[10];
    float* out = (float*)d_out;

    void *gxb, *gwq, *gwk, *gwv, *gwo, *gq, *gk, *gv, *go, *gp;
    cudaGetSymbolAddress(&gxb, g_xb);
    cudaGetSymbolAddress(&gwq, g_Wqb);
    cudaGetSymbolAddress(&gwk, g_Wkb);
    cudaGetSymbolAddress(&gwv, g_Wvb);
    cudaGetSymbolAddress(&gwo, g_Wob);
    cudaGetSymbolAddress(&gq,  g_Q);
    cudaGetSymbolAddress(&gk,  g_K);
    cudaGetSymbolAddress(&gv,  g_V);
    cudaGetSymbolAddress(&go,  g_O);
    cudaGetSymbolAddress(&gp,  g_P);

    void* fp = nullptr;
    cudaDriverEntryPointQueryResult st;
    cudaGetDriverEntryPointByVersion("cuTensorMapEncodeTiled", &fp, 12000,
                                     cudaEnableDefault, &st);
    PFN_tmencode enc = (PFN_tmencode)fp;

    CUtensorMap tmX, tmO, tmWq, tmWk, tmWv, tmWo, tmQ, tmK, tmV;
    // activations [4096 m][1024 k] bf16: box 64k x 128m
    mkmap_bf16(enc, &tmX, gxb, 1024, 4096, 2048ULL, 64, 128);
    mkmap_bf16(enc, &tmO, go,  1024, 4096, 2048ULL, 64, 128);
    // weights [1024 k][1024 n] bf16: box 64n x 64k
    mkmap_bf16(enc, &tmWq, gwq, 1024, 1024, 2048ULL, 64, 64);
    mkmap_bf16(enc, &tmWk, gwk, 1024, 1024, 2048ULL, 64, 64);
    mkmap_bf16(enc, &tmWv, gwv, 1024, 1024, 2048ULL, 64, 64);
    mkmap_bf16(enc, &tmWo, gwo, 1024, 1024, 2048ULL, 64, 64);
    // Q/K/V [65536 rows][64 d] bf16 (stride 128B)
    mkmap_bf16(enc, &tmQ, gq, 64, (unsigned long long)Bn * Hn * Tn, 128ULL, 64, 128);
    mkmap_bf16(enc, &tmK, gk, 64, (unsigned long long)Bn * Hn * Tn, 128ULL, 64, 64);
    mkmap_bf16(enc, &tmV, gv, 64, (unsigned long long)Bn * Hn * Tn, 128ULL, 64, 64);

    cudaFuncSetAttribute(qkv_gemm, cudaFuncAttributeMaxDynamicSharedMemorySize,
                         GEMM_DSMEM);
    cudaFuncSetAttribute(oproj_gemm, cudaFuncAttributeMaxDynamicSharedMemorySize,
                         GEMM_DSMEM);
    cudaFuncSetAttribute(attn_tc, cudaFuncAttributeMaxDynamicSharedMemorySize,
                         ATT_DSMEM);

    cvt_bf16<<<dim3(4096, 1, 5), 256>>>(x, Wq, Wk, Wv, Wo);

    qkv_gemm<<<dim3(Dn / 128, Mn / 128, 3), 256, GEMM_DSMEM>>>(
        tmX, tmWq, tmWk, tmWv, bq, bk, bv);

    attn_tc<<<dim3(Tn / 128, Bn * Hn), 256, ATT_DSMEM>>>(tmQ, tmK, tmV);

    oproj_gemm<<<dim3(Dn / 128, Mn / 128), 256, GEMM_DSMEM>>>(tmO, tmWo, bo, x);

    ln_kernel<<<Mn, 256>>>((const float*)gp, lg, lb, out);
}

// round 9
// speedup vs baseline: 2.8951x; 1.0708x over previous
#include <cuda_runtime.h>
#include <cuda.h>
#include <cuda_fp16.h>
#include <math.h>
#include <stdint.h>

#define Bn  2
#define Tn  2048
#define Dn  1024
#define Hn  16
#define HDn 64
#define Mn  (Bn * Tn)   // 4096

// -------- scratch (static device globals; no allocations allowed) --------
__device__ __half2 g_xb[(size_t)Mn * Dn / 2];            // x f16 [4096][1024]
__device__ __half2 g_Wqb[(size_t)Dn * Dn / 2];           // W f16 [k][n]
__device__ __half2 g_Wkb[(size_t)Dn * Dn / 2];
__device__ __half2 g_Wvb[(size_t)Dn * Dn / 2];
__device__ __half2 g_Wob[(size_t)Dn * Dn / 2];
__device__ unsigned g_Q[(size_t)Bn * Hn * Tn * HDn / 2]; // f16x2 [bh*T+t][32]
__device__ unsigned g_K[(size_t)Bn * Hn * Tn * HDn / 2];
__device__ unsigned g_V[(size_t)Bn * Hn * Tn * HDn / 2];
__device__ unsigned g_O[(size_t)Mn * Dn / 2];            // f16x2 [B*T][512]
__device__ float    g_P[(size_t)Mn * Dn];                // pre-LN fp32

// ---------------- helpers ----------------
__device__ __forceinline__ uint32_t s2u(const void* p) {
    return (uint32_t)__cvta_generic_to_shared(p);
}
__device__ __forceinline__ unsigned pkh(float a, float b) {
    __half2 t = __float22half2_rn(make_float2(a, b));
    return *(unsigned*)&t;
}
__device__ __forceinline__ float ex2(float x) {
    float y;
    asm("ex2.approx.f32 %0, %1;" : "=f"(y) : "f"(x));
    return y;
}
__device__ __forceinline__ unsigned hex2(unsigned x) {
    unsigned y;
    asm("ex2.approx.f16x2 %0, %1;" : "=r"(y) : "r"(x));
    return y;
}
// SW128 swizzle on byte offset within a tile of 128B rows
__device__ __forceinline__ uint32_t swz(uint32_t o) {
    return o ^ ((o >> 3) & 0x70);
}
// D += A(16x16) * B(16x8), f16 in, f32 accum
__device__ __forceinline__ void mma16(float* d, const unsigned* a,
                                      unsigned b0, unsigned b1) {
    asm volatile(
        "mma.sync.aligned.m16n8k16.row.col.f32.f16.f16.f32 "
        "{%0,%1,%2,%3},{%4,%5,%6,%7},{%8,%9},{%0,%1,%2,%3};"
        : "+f"(d[0]), "+f"(d[1]), "+f"(d[2]), "+f"(d[3])
        : "r"(a[0]), "r"(a[1]), "r"(a[2]), "r"(a[3]), "r"(b0), "r"(b1));
}
__device__ __forceinline__ void ldsm_x4(unsigned* r, uint32_t a) {
    asm volatile("ldmatrix.sync.aligned.m8n8.x4.shared.b16 {%0,%1,%2,%3}, [%4];"
        : "=r"(r[0]), "=r"(r[1]), "=r"(r[2]), "=r"(r[3]) : "r"(a));
}
__device__ __forceinline__ void ldsm_x4t(unsigned* r, uint32_t a) {
    asm volatile("ldmatrix.sync.aligned.m8n8.x4.trans.shared.b16 {%0,%1,%2,%3}, [%4];"
        : "=r"(r[0]), "=r"(r[1]), "=r"(r[2]), "=r"(r[3]) : "r"(a));
}
__device__ __forceinline__ void mbar_init(uint32_t m, uint32_t cnt) {
    asm volatile("mbarrier.init.shared.b64 [%0], %1;" :: "r"(m), "r"(cnt) : "memory");
}
__device__ __forceinline__ void mbar_expect(uint32_t m, uint32_t bytes) {
    asm volatile("mbarrier.arrive.expect_tx.shared.b64 _, [%0], %1;"
                 :: "r"(m), "r"(bytes) : "memory");
}
__device__ __forceinline__ void mbar_wait(uint32_t m, uint32_t parity) {
    asm volatile(
        "{\n\t.reg .pred P1;\n\t"
        "WAIT_%=:\n\t"
        "mbarrier.try_wait.parity.acquire.cta.shared::cta.b64 P1, [%0], %1, 0x989680;\n\t"
        "@P1 bra.uni DONE_%=;\n\t"
        "bra.uni WAIT_%=;\n\t"
        "DONE_%=:\n\t}"
        :: "r"(m), "r"(parity) : "memory");
}
__device__ __forceinline__ void tma2d(uint32_t dst, const CUtensorMap* tm,
                                      int x, int y, uint32_t mbar) {
    asm volatile(
        "cp.async.bulk.tensor.2d.shared::cta.global.tile.mbarrier::complete_tx::bytes "
        "[%0], [%1, {%2, %3}], [%4];"
        :: "r"(dst), "l"(tm), "r"(x), "r"(y), "r"(mbar) : "memory");
}

#define ONESH 0x3C003C00u    // f16x2 (1.0, 1.0)

// =========================================================================
// f16 conversion pre-pass (x + 4 weights)
// =========================================================================
__global__ void __launch_bounds__(256) cvt_f16(
    const float* __restrict__ x,
    const float* __restrict__ wq, const float* __restrict__ wk,
    const float* __restrict__ wv, const float* __restrict__ wo)
{
    const float* src; __half2* dst; int n4;
    switch (blockIdx.z) {
        case 0: src = x;  dst = g_xb;  n4 = Mn * Dn / 4; break;
        case 1: src = wq; dst = g_Wqb; n4 = Dn * Dn / 4; break;
        case 2: src = wk; dst = g_Wkb; n4 = Dn * Dn / 4; break;
        case 3: src = wv; dst = g_Wvb; n4 = Dn * Dn / 4; break;
        default: src = wo; dst = g_Wob; n4 = Dn * Dn / 4; break;
    }
    int i = blockIdx.x * 256 + threadIdx.x;
    if (i < n4) {
        float4 v = ((const float4*)src)[i];
        dst[2 * i]     = __float22half2_rn(make_float2(v.x, v.y));
        dst[2 * i + 1] = __float22half2_rn(make_float2(v.z, v.w));
    }
}

// =========================================================================
// f16 GEMM, 128x128 CTA tile, K-chunk 64, 3-stage TMA pipeline.
// 256 threads = 8 warps (4m x 2n). Stage 32KB:
//   A [128 m][64 k] SW128 (16KB) | B 2 subtiles [64 k][64 n] SW128 (8KB each)
// =========================================================================
#define G_STG 32768
#define GEMM_DSMEM (3 * G_STG + 1024)

__device__ __forceinline__ void gemm_main(
    const CUtensorMap* tmA, const CUtensorMap* tmB,
    const float* __restrict__ bias, const float* __restrict__ resid,
    unsigned* out_q, float* out_f, int mode, float scale)
{
    extern __shared__ char smraw[];
    char* smb = (char*)(((uintptr_t)smraw + 1023) & ~(uintptr_t)1023);
    __shared__ uint64_t mb[3];

    const int tid = threadIdx.x, lane = tid & 31, w = tid >> 5;
    const int g = lane >> 2, tig = lane & 3;
    const int wm = w & 3, wn = w >> 2;
    const int l15 = lane & 15, lhi = (lane >> 4) & 1;
    const int m0 = blockIdx.y * 128, n0 = blockIdx.x * 128;
    const uint32_t smu = s2u(smb);

    if (tid == 0)
        for (int s = 0; s < 3; s++) mbar_init(s2u(&mb[s]), 1);
    __syncthreads();
    if (tid == 0) {
        for (int s = 0; s < 2; s++) {       // chunks 0,1 -> slots 0,1
            uint32_t st = smu + s * G_STG;
            mbar_expect(s2u(&mb[s]), G_STG);
            tma2d(st,          tmA, s * 64,  m0,     s2u(&mb[s]));
            tma2d(st + 16384,  tmB, n0,      s * 64, s2u(&mb[s]));
            tma2d(st + 24576,  tmB, n0 + 64, s * 64, s2u(&mb[s]));
        }
    }

    float acc[2][8][4];
#pragma unroll
    for (int mt = 0; mt < 2; mt++)
#pragma unroll
        for (int nt = 0; nt < 8; nt++)
#pragma unroll
            for (int j = 0; j < 4; j++) acc[mt][nt][j] = 0.f;

    for (int c = 0; c < 16; c++) {
        mbar_wait(s2u(&mb[c % 3]), (c / 3) & 1);
        __syncthreads();                    // all warps done with slot (c-1)%3
        if (tid == 0 && c + 2 < 16) {
            int s = (c + 2) % 3;
            uint32_t st = smu + s * G_STG;
            mbar_expect(s2u(&mb[s]), G_STG);
            tma2d(st,          tmA, (c + 2) * 64, m0,           s2u(&mb[s]));
            tma2d(st + 16384,  tmB, n0,           (c + 2) * 64, s2u(&mb[s]));
            tma2d(st + 24576,  tmB, n0 + 64,      (c + 2) * 64, s2u(&mb[s]));
        }

        const uint32_t as_b = smu + (c % 3) * G_STG;
        const uint32_t bs_b = as_b + 16384 + wn * 8192;

#pragma unroll
        for (int kk = 0; kk < 4; kk++) {
            unsigned av[2][4];
#pragma unroll
            for (int mt = 0; mt < 2; mt++)
                ldsm_x4(av[mt], as_b + swz((wm * 32 + mt * 16 + l15) * 128
                                           + (kk * 16 + lhi * 8) * 2));
#pragma unroll
            for (int ntp = 0; ntp < 4; ntp++) {
                unsigned bv[4];
                ldsm_x4t(bv, bs_b + swz((kk * 16 + l15) * 128
                                        + (ntp * 16 + lhi * 8) * 2));
                mma16(acc[0][2 * ntp],     av[0], bv[0], bv[1]);
                mma16(acc[1][2 * ntp],     av[1], bv[0], bv[1]);
                mma16(acc[0][2 * ntp + 1], av[0], bv[2], bv[3]);
                mma16(acc[1][2 * ntp + 1], av[1], bv[2], bv[3]);
            }
        }
    }

    // epilogue
#pragma unroll
    for (int mt = 0; mt < 2; mt++) {
#pragma unroll
        for (int nt = 0; nt < 8; nt++) {
            int r0 = m0 + wm * 32 + mt * 16 + g;
            int n = n0 + wn * 64 + nt * 8 + 2 * tig;
            float bx = bias[n], by = bias[n + 1];
            if (mode == 0) {
#pragma unroll
                for (int rp = 0; rp < 2; rp++) {
                    int r = r0 + rp * 8;
                    int bb = r >> 11, t = r & (Tn - 1);
                    int h = n >> 6, hd = n & 63;
                    float v0 = (acc[mt][nt][2 * rp]     + bx) * scale;
                    float v1 = (acc[mt][nt][2 * rp + 1] + by) * scale;
                    out_q[(((size_t)(bb * Hn + h) * Tn + t) << 5) + (hd >> 1)] = pkh(v0, v1);
                }
            } else {
#pragma unroll
                for (int rp = 0; rp < 2; rp++) {
                    int r = r0 + rp * 8;
                    size_t off = (size_t)r * Dn + n;
                    float2 rv = *(const float2*)&resid[off];
                    float2 val = make_float2(acc[mt][nt][2 * rp] + bx + rv.x,
                                             acc[mt][nt][2 * rp + 1] + by + rv.y);
                    *(float2*)&out_f[off] = val;
                }
            }
        }
    }
}

// Q is scaled by (1/8)*log2(e) so softmax can run in exp2 domain.
#define QSCALE 0.18033688f

__global__ void __launch_bounds__(256, 2) qkv_gemm(
    const __grid_constant__ CUtensorMap tmA,
    const __grid_constant__ CUtensorMap tmq,
    const __grid_constant__ CUtensorMap tmk,
    const __grid_constant__ CUtensorMap tmv,
    const float* __restrict__ bq, const float* __restrict__ bk,
    const float* __restrict__ bv)
{
    const CUtensorMap* tb; const float* b; unsigned* o; float scale;
    if (blockIdx.z == 0)      { tb = &tmq; b = bq; o = g_Q; scale = QSCALE; }
    else if (blockIdx.z == 1) { tb = &tmk; b = bk; o = g_K; scale = 1.f; }
    else                      { tb = &tmv; b = bv; o = g_V; scale = 1.f; }
    gemm_main(&tmA, tb, b, nullptr, o, nullptr, 0, scale);
}

__global__ void __launch_bounds__(256, 2) oproj_gemm(
    const __grid_constant__ CUtensorMap tmA,
    const __grid_constant__ CUtensorMap tmW,
    const float* __restrict__ bo, const float* __restrict__ resid)
{
    gemm_main(&tmA, &tmW, bo, resid, nullptr, g_P, 1, 1.f);
}

// =========================================================================
// f16 flash attention, TMA loads. CTA = (bh, 128 query rows), 8 warps.
// K-tiles of 64, 3-stage pipeline. smem: Q[128][64] SW128 (16KB) |
// 3 stages x { K[64][64] SW128 8KB, V[64][64] SW128 8KB }.
// Softmax: exp2 domain, ex2.approx.f16x2 producing P fragments directly;
// row denominators accumulated via a ones-column mma (l = P @ 1).
// =========================================================================
#define A_STG 16384
#define ATT_DSMEM (16384 + 3 * A_STG + 1024)

__global__ void __launch_bounds__(256, 2) attn_tc(
    const __grid_constant__ CUtensorMap tmQ,
    const __grid_constant__ CUtensorMap tmK,
    const __grid_constant__ CUtensorMap tmV)
{
    extern __shared__ char smraw[];
    char* smb = (char*)(((uintptr_t)smraw + 1023) & ~(uintptr_t)1023);
    __shared__ uint64_t mbq, mb[3];

    const int tid = threadIdx.x, lane = tid & 31, w = tid >> 5;
    const int l15 = lane & 15, lhi = (lane >> 4) & 1, l8 = (lane >> 3) & 1;
    const int g = lane >> 2, tig = lane & 3;
    const int bh = blockIdx.y;
    const int q0 = blockIdx.x << 7;
    const int b = bh >> 4, h = bh & 15;
    const int rb = w * 16;
    const int krow0 = bh * Tn;
    const uint32_t smu = s2u(smb);
    const uint32_t qs_b = smu, buf = smu + 16384;

    if (tid == 0) {
        mbar_init(s2u(&mbq), 1);
        for (int s = 0; s < 3; s++) mbar_init(s2u(&mb[s]), 1);
    }
    __syncthreads();
    if (tid == 0) {
        mbar_expect(s2u(&mbq), 16384);
        tma2d(qs_b, &tmQ, 0, krow0 + q0, s2u(&mbq));
        for (int s = 0; s < 2; s++) {
            uint32_t st = buf + s * A_STG;
            mbar_expect(s2u(&mb[s]), A_STG);
            tma2d(st,        &tmK, 0, krow0 + s * 64, s2u(&mb[s]));
            tma2d(st + 8192, &tmV, 0, krow0 + s * 64, s2u(&mb[s]));
        }
    }

    // Q fragments (Q pre-scaled by log2e/8 at creation)
    mbar_wait(s2u(&mbq), 0);
    unsigned qa[4][4];
#pragma unroll
    for (int kk = 0; kk < 4; kk++)
        ldsm_x4(qa[kk], qs_b + swz((rb + l15) * 128 + (kk * 16 + lhi * 8) * 2));

    float oacc[8][4], lacc[4];
#pragma unroll
    for (int nt = 0; nt < 8; nt++)
#pragma unroll
        for (int j = 0; j < 4; j++) oacc[nt][j] = 0.f;
#pragma unroll
    for (int j = 0; j < 4; j++) lacc[j] = 0.f;
    float mst0 = -1e30f, mst1 = -1e30f;

    for (int it = 0; it < 32; it++) {
        mbar_wait(s2u(&mb[it % 3]), (it / 3) & 1);
        __syncthreads();                      // slot (it-1)%3 fully consumed
        if (tid == 0 && it + 2 < 32) {
            int s = (it + 2) % 3;
            uint32_t st = buf + s * A_STG;
            mbar_expect(s2u(&mb[s]), A_STG);
            tma2d(st,        &tmK, 0, krow0 + (it + 2) * 64, s2u(&mb[s]));
            tma2d(st + 8192, &tmV, 0, krow0 + (it + 2) * 64, s2u(&mb[s]));
        }

        const uint32_t ks_b = buf + (it % 3) * A_STG;
        const uint32_t vs_b = ks_b + 8192;

        // ---- S = Q K^T (exp2 domain) ----
        float sacc[8][4];
#pragma unroll
        for (int nt = 0; nt < 8; nt++)
#pragma unroll
            for (int j = 0; j < 4; j++) sacc[nt][j] = 0.f;

#pragma unroll
        for (int kk = 0; kk < 4; kk++) {
#pragma unroll
            for (int ntp = 0; ntp < 4; ntp++) {
                unsigned kb[4];
                ldsm_x4(kb, ks_b + swz((ntp * 16 + (lane & 7) + lhi * 8) * 128
                                       + (kk * 16 + l8 * 8) * 2));
                mma16(sacc[2 * ntp],     qa[kk], kb[0], kb[1]);
                mma16(sacc[2 * ntp + 1], qa[kk], kb[2], kb[3]);
            }
        }

        // ---- max update (row quads: lanes xor 1,2), base-2 ----
        float mx0 = -1e30f, mx1 = -1e30f;
#pragma unroll
        for (int nt = 0; nt < 8; nt++) {
            mx0 = fmaxf(mx0, fmaxf(sacc[nt][0], sacc[nt][1]));
            mx1 = fmaxf(mx1, fmaxf(sacc[nt][2], sacc[nt][3]));
        }
        mx0 = fmaxf(mx0, __shfl_xor_sync(0xffffffffu, mx0, 1));
        mx0 = fmaxf(mx0, __shfl_xor_sync(0xffffffffu, mx0, 2));
        mx1 = fmaxf(mx1, __shfl_xor_sync(0xffffffffu, mx1, 1));
        mx1 = fmaxf(mx1, __shfl_xor_sync(0xffffffffu, mx1, 2));
        float mn0 = fmaxf(mst0, mx0), mn1 = fmaxf(mst1, mx1);
        float c0 = ex2(mst0 - mn0), c1 = ex2(mst1 - mn1);
        mst0 = mn0; mst1 = mn1;
#pragma unroll
        for (int nt = 0; nt < 8; nt++) {
            oacc[nt][0] *= c0; oacc[nt][1] *= c0;
            oacc[nt][2] *= c1; oacc[nt][3] *= c1;
        }
        lacc[0] *= c0; lacc[1] *= c0; lacc[2] *= c1; lacc[3] *= c1;

        // ---- O += P V ; l += P 1  (P built by f16x2 exp2, stays in regs) ----
#pragma unroll
        for (int kk = 0; kk < 4; kk++) {
            unsigned pa[4];
            pa[0] = hex2(pkh(sacc[2 * kk][0] - mn0,     sacc[2 * kk][1] - mn0));
            pa[1] = hex2(pkh(sacc[2 * kk][2] - mn1,     sacc[2 * kk][3] - mn1));
            pa[2] = hex2(pkh(sacc[2 * kk + 1][0] - mn0, sacc[2 * kk + 1][1] - mn0));
            pa[3] = hex2(pkh(sacc[2 * kk + 1][2] - mn1, sacc[2 * kk + 1][3] - mn1));
            mma16(lacc, pa, ONESH, ONESH);
#pragma unroll
            for (int ntp = 0; ntp < 4; ntp++) {
                unsigned vb[4];
                ldsm_x4t(vb, vs_b + swz((kk * 16 + l15) * 128
                                        + (ntp * 16 + lhi * 8) * 2));
                mma16(oacc[2 * ntp],     pa, vb[0], vb[1]);
                mma16(oacc[2 * ntp + 1], pa, vb[2], vb[3]);
            }
        }
    }

    // epilogue -> f16 O [B*T][1024]
    float i0 = 1.f / lacc[0], i1 = 1.f / lacc[2];
    int gr0 = b * Tn + q0 + rb + g;
#pragma unroll
    for (int nt = 0; nt < 8; nt++) {
        int col = h * HDn + nt * 8 + 2 * tig;
        g_O[(size_t)gr0 * 512 + (col >> 1)] =
            pkh(oacc[nt][0] * i0, oacc[nt][1] * i0);
        g_O[(size_t)(gr0 + 8) * 512 + (col >> 1)] =
            pkh(oacc[nt][2] * i1, oacc[nt][3] * i1);
    }
}

// =========================================================================
// LayerNorm: 1 block per row, 256 threads, 1 float4 per thread.
// =========================================================================
__global__ void __launch_bounds__(256) ln_kernel(
    const float* __restrict__ P, const float* __restrict__ gw,
    const float* __restrict__ gb, float* __restrict__ out)
{
    const int row = blockIdx.x;
    const int tid = threadIdx.x;
    const float4 v = ((const float4*)(P + (size_t)row * Dn))[tid];

    float s  = v.x + v.y + v.z + v.w;
    float ss = v.x * v.x + v.y * v.y + v.z * v.z + v.w * v.w;
#pragma unroll
    for (int off = 16; off; off >>= 1) {
        s  += __shfl_xor_sync(0xffffffffu, s, off);
        ss += __shfl_xor_sync(0xffffffffu, ss, off);
    }
    __shared__ float sh_s[8], sh_ss[8];
    const int w = tid >> 5, lane = tid & 31;
    if (lane == 0) { sh_s[w] = s; sh_ss[w] = ss; }
    __syncthreads();
    if (w == 0) {
        float s2  = (lane < 8) ? sh_s[lane]  : 0.f;
        float ss2 = (lane < 8) ? sh_ss[lane] : 0.f;
#pragma unroll
        for (int off = 4; off; off >>= 1) {
            s2  += __shfl_xor_sync(0xffffffffu, s2, off);
            ss2 += __shfl_xor_sync(0xffffffffu, ss2, off);
        }
        if (lane == 0) { sh_s[0] = s2; sh_ss[0] = ss2; }
    }
    __syncthreads();

    const float mu  = sh_s[0] * (1.0f / Dn);
    const float var = sh_ss[0] * (1.0f / Dn) - mu * mu;
    const float rs  = rsqrtf(var + 1e-5f);

    const float4 g = ((const float4*)gw)[tid];
    const float4 bb = ((const float4*)gb)[tid];
    float4 r;
    r.x = (v.x - mu) * rs * g.x + bb.x;
    r.y = (v.y - mu) * rs * g.y + bb.y;
    r.z = (v.z - mu) * rs * g.z + bb.z;
    r.w = (v.w - mu) * rs * g.w + bb.w;
    ((float4*)(out + (size_t)row * Dn))[tid] = r;
}

// =========================================================================
// Host
// =========================================================================
typedef CUresult (*PFN_tmencode)(
    CUtensorMap*, CUtensorMapDataType, cuuint32_t, void*,
    const cuuint64_t*, const cuuint64_t*, const cuuint32_t*, const cuuint32_t*,
    CUtensorMapInterleave, CUtensorMapSwizzle, CUtensorMapL2promotion,
    CUtensorMapFloatOOBfill);

static void mkmap_f16(PFN_tmencode enc, CUtensorMap* tm, const void* ptr,
                      unsigned long long d0, unsigned long long d1,
                      unsigned long long stride_bytes, unsigned b0, unsigned b1)
{
    cuuint64_t dims[2] = {(cuuint64_t)d0, (cuuint64_t)d1};
    cuuint64_t str[1]  = {(cuuint64_t)stride_bytes};
    cuuint32_t box[2]  = {b0, b1};
    cuuint32_t es[2]   = {1, 1};
    enc(tm, CU_TENSOR_MAP_DATA_TYPE_FLOAT16, 2, (void*)ptr, dims, str, box, es,
        CU_TENSOR_MAP_INTERLEAVE_NONE, CU_TENSOR_MAP_SWIZZLE_128B,
        CU_TENSOR_MAP_L2_PROMOTION_L2_128B, CU_TENSOR_MAP_FLOAT_OOB_FILL_NONE);
}

extern "C" void kernel_launch(void* const* d_in, const int* in_sizes, int n_in,
                              void* d_out, int out_size)
{
    const float* x  = (const float*)d_in[0];
    const float* Wq = (const float*)d_in[1];
    const float* bq = (const float*)d_in[2];
    const float* Wk = (const float*)d_in[3];
    const float* bk = (const float*)d_in[4];
    const float* Wv = (const float*)d_in[5];
    const float* bv = (const float*)d_in[6];
    const float* Wo = (const float*)d_in[7];
    const float* bo = (const float*)d_in[8];
    const float* lg = (const float*)d_in[9];
    const float* lb = (const float*)d_in[10];
    float* out = (float*)d_out;

    void *gxb, *gwq, *gwk, *gwv, *gwo, *gq, *gk, *gv, *go, *gp;
    cudaGetSymbolAddress(&gxb, g_xb);
    cudaGetSymbolAddress(&gwq, g_Wqb);
    cudaGetSymbolAddress(&gwk, g_Wkb);
    cudaGetSymbolAddress(&gwv, g_Wvb);
    cudaGetSymbolAddress(&gwo, g_Wob);
    cudaGetSymbolAddress(&gq,  g_Q);
    cudaGetSymbolAddress(&gk,  g_K);
    cudaGetSymbolAddress(&gv,  g_V);
    cudaGetSymbolAddress(&go,  g_O);
    cudaGetSymbolAddress(&gp,  g_P);

    void* fp = nullptr;
    cudaDriverEntryPointQueryResult st;
    cudaGetDriverEntryPointByVersion("cuTensorMapEncodeTiled", &fp, 12000,
                                     cudaEnableDefault, &st);
    PFN_tmencode enc = (PFN_tmencode)fp;

    CUtensorMap tmX, tmO, tmWq, tmWk, tmWv, tmWo, tmQ, tmK, tmV;
    // activations [4096 m][1024 k] f16: box 64k x 128m
    mkmap_f16(enc, &tmX, gxb, 1024, 4096, 2048ULL, 64, 128);
    mkmap_f16(enc, &tmO, go,  1024, 4096, 2048ULL, 64, 128);
    // weights [1024 k][1024 n] f16: box 64n x 64k
    mkmap_f16(enc, &tmWq, gwq, 1024, 1024, 2048ULL, 64, 64);
    mkmap_f16(enc, &tmWk, gwk, 1024, 1024, 2048ULL, 64, 64);
    mkmap_f16(enc, &tmWv, gwv, 1024, 1024, 2048ULL, 64, 64);
    mkmap_f16(enc, &tmWo, gwo, 1024, 1024, 2048ULL, 64, 64);
    // Q/K/V [65536 rows][64 d] f16 (stride 128B)
    mkmap_f16(enc, &tmQ, gq, 64, (unsigned long long)Bn * Hn * Tn, 128ULL, 64, 128);
    mkmap_f16(enc, &tmK, gk, 64, (unsigned long long)Bn * Hn * Tn, 128ULL, 64, 64);
    mkmap_f16(enc, &tmV, gv, 64, (unsigned long long)Bn * Hn * Tn, 128ULL, 64, 64);

    cudaFuncSetAttribute(qkv_gemm, cudaFuncAttributeMaxDynamicSharedMemorySize,
                         GEMM_DSMEM);
    cudaFuncSetAttribute(oproj_gemm, cudaFuncAttributeMaxDynamicSharedMemorySize,
                         GEMM_DSMEM);
    cudaFuncSetAttribute(attn_tc, cudaFuncAttributeMaxDynamicSharedMemorySize,
                         ATT_DSMEM);

    cvt_f16<<<dim3(4096, 1, 5), 256>>>(x, Wq, Wk, Wv, Wo);

    qkv_gemm<<<dim3(Dn / 128, Mn / 128, 3), 256, GEMM_DSMEM>>>(
        tmX, tmWq, tmWk, tmWv, bq, bk, bv);

    attn_tc<<<dim3(Tn / 128, Bn * Hn), 256, ATT_DSMEM>>>(tmQ, tmK, tmV);

    oproj_gemm<<<dim3(Dn / 128, Mn / 128), 256, GEMM_DSMEM>>>(tmO, tmWo, bo, x);

    ln_kernel<<<Mn, 256>>>((const float*)gp, lg, lb, out);
}